// round 13
// baseline (speedup 1.0000x reference)
#include <cuda_runtime.h>
#include <cuda_fp16.h>
#include <math.h>
#include <stdint.h>

#define B_    8
#define D_    512
#define H_    8
#define DH_   64
#define L_    6
#define DFF_  2048
#define CIN_  2048
#define SEQ_  912
#define NTOK_ 911
#define DMLP_ 1024
#define QKVOFF ((long)B_ * SEQ_ * D_)

// ---------------- scratch (static device globals; allocation-free) ----------
__device__ __align__(16) __half g_Ah[(size_t)B_ * NTOK_ * CIN_];
__device__ __align__(16) float  g_add[(size_t)NTOK_ * D_];
__device__ __align__(16) float  g_x[(size_t)B_ * SEQ_ * D_];
__device__ __align__(16) __half g_xh[(size_t)B_ * SEQ_ * D_];
__device__ __align__(16) float  g_tmp[(size_t)B_ * SEQ_ * D_];
__device__ __align__(16) __half g_qkvh[3 * (size_t)B_ * SEQ_ * D_];
__device__ __align__(16) __half g_ctxh[(size_t)B_ * SEQ_ * D_];
__device__ __align__(16) __half g_ffh[(size_t)B_ * SEQ_ * DFF_];
__device__ __align__(16) __half g_wqkv[(size_t)L_ * 3 * D_ * D_];
__device__ __align__(16) __half g_woh[(size_t)L_ * D_ * D_];
__device__ __align__(16) __half g_w1h[(size_t)L_ * DFF_ * D_];
__device__ __align__(16) __half g_w2h[(size_t)L_ * D_ * DFF_];
__device__ __align__(16) __half g_cwh[(size_t)D_ * CIN_];
// last-layer compact cls-path buffers
__device__ __align__(16) __half g_c8h[(size_t)B_ * D_];
__device__ __align__(16) float  g_x8[(size_t)B_ * D_];
__device__ __align__(16) float  g_t8[(size_t)B_ * D_];
__device__ __align__(16) __half g_x8h[(size_t)B_ * D_];
__device__ __align__(16) __half g_f8h[(size_t)B_ * DFF_];

__device__ __forceinline__ float gelu_exact(float x) {
    return 0.5f * x * (1.0f + erff(x * 0.70710678118654752f));
}
__device__ __forceinline__ uint32_t smem_u32(const void* p) {
    uint32_t a;
    asm("{ .reg .u64 t; cvta.to.shared.u64 t, %1; cvt.u32.u64 %0, t; }"
        : "=r"(a) : "l"(p));
    return a;
}
__device__ __forceinline__ uint32_t packh2(float x, float y) {
    __half2 h = __floats2half2_rn(x, y);
    return *(uint32_t*)&h;
}
__device__ __forceinline__ void mma_f16(float c[4], const uint32_t a[4],
                                        uint32_t b0, uint32_t b1) {
    asm volatile(
        "mma.sync.aligned.m16n8k16.row.col.f32.f16.f16.f32 "
        "{%0,%1,%2,%3}, {%4,%5,%6,%7}, {%8,%9}, {%0,%1,%2,%3};"
        : "+f"(c[0]), "+f"(c[1]), "+f"(c[2]), "+f"(c[3])
        : "r"(a[0]), "r"(a[1]), "r"(a[2]), "r"(a[3]), "r"(b0), "r"(b1));
}
#define LDSM_X4(r, addr) \
    asm volatile("ldmatrix.sync.aligned.m8n8.x4.shared.b16 {%0,%1,%2,%3}, [%4];" \
        : "=r"((r)[0]), "=r"((r)[1]), "=r"((r)[2]), "=r"((r)[3]) : "r"(addr))
#define LDSM_X4_T(r, addr) \
    asm volatile("ldmatrix.sync.aligned.m8n8.x4.trans.shared.b16 {%0,%1,%2,%3}, [%4];" \
        : "=r"((r)[0]), "=r"((r)[1]), "=r"((r)[2]), "=r"((r)[3]) : "r"(addr))
#define CP_ASYNC(dst, src, sz) \
    asm volatile("cp.async.cg.shared.global [%0], [%1], 16, %2;" \
                 :: "r"(dst), "l"(src), "r"(sz) : "memory")
#define CP_COMMIT() asm volatile("cp.async.commit_group;" ::: "memory")
#define CP_WAIT2()  asm volatile("cp.async.wait_group 2;" ::: "memory")
#define CP_WAIT1()  asm volatile("cp.async.wait_group 1;" ::: "memory")
#define CP_WAIT0()  asm volatile("cp.async.wait_group 0;" ::: "memory")

// ---------------- single staging kernel: all weights -> half -----------------
__global__ void stage_k(const float* __restrict__ conv_w,
                        const float* __restrict__ Wo,
                        const float* __restrict__ w1,
                        const float* __restrict__ w2,
                        const float* __restrict__ Wq,
                        const float* __restrict__ Wk,
                        const float* __restrict__ Wv,
                        __half* __restrict__ cwh, __half* __restrict__ woh,
                        __half* __restrict__ w1h, __half* __restrict__ w2h,
                        __half* __restrict__ wqkv)
{
    const long n0 = (long)D_ * CIN_ / 4;
    const long n1 = (long)L_ * D_ * D_ / 4;
    const long n2 = (long)L_ * DFF_ * D_ / 4;
    const long n3 = (long)L_ * D_ * DFF_ / 4;
    const long n4 = (long)L_ * 3 * D_ * D_ / 4;
    const long total = n0 + n1 + n2 + n3 + n4;
    const long per = (long)D_ * D_ / 4;

    for (long i = (long)blockIdx.x * blockDim.x + threadIdx.x; i < total;
         i += (long)gridDim.x * blockDim.x) {
        const float* src;
        __half* dst;
        long so, dd;
        if (i < n0)                { src = conv_w; dst = cwh; so = i; dd = i; }
        else if (i < n0 + n1)      { src = Wo; dst = woh; so = i - n0; dd = so; }
        else if (i < n0 + n1 + n2) { src = w1; dst = w1h; so = i - n0 - n1; dd = so; }
        else if (i < n0 + n1 + n2 + n3) {
            src = w2; dst = w2h; so = i - n0 - n1 - n2; dd = so;
        } else {
            long r = i - n0 - n1 - n2 - n3;
            long l = r / (3 * per);
            long q = (r / per) % 3;
            long o = r % per;
            src = (q == 0 ? Wq : (q == 1 ? Wk : Wv));
            so = l * per + o;
            dst = wqkv; dd = r;
        }
        float4 v = *((const float4*)src + so);
        __half2* d = (__half2*)(dst + dd * 4);
        d[0] = __floats2half2_rn(v.x, v.y);
        d[1] = __floats2half2_rn(v.z, v.w);
    }
}

// ---------------- cp.async + ldmatrix FP16 GEMM: C = A(MxK)*B(NxK)^T ---------
#define STAGES 3
#define TILEB  16384
#define GSMEM  (STAGES * 2 * TILEB)

template <int MODE>
__global__ __launch_bounds__(256, 2) void gemm_cp(
    const __half* __restrict__ A, const __half* __restrict__ Bm,
    float* __restrict__ C, __half* __restrict__ Ch, int M, int N, int K,
    const float* __restrict__ bias,
    const float* __restrict__ res,
    const float* __restrict__ rowadd)
{
    extern __shared__ char smraw[];
    const uint32_t sb = smem_u32(smraw);
    const int tid  = threadIdx.x;
    const int lane = tid & 31;
    const int wid  = tid >> 5;
    const int wm   = wid & 1;
    const int wn   = wid >> 1;
    const int row0 = blockIdx.y * 128;
    const int col0 = blockIdx.x * 128;

    const int ldr = tid >> 3;
    const int ldc = tid & 7;

    float acc[4][4][4];
#pragma unroll
    for (int i = 0; i < 4; i++)
#pragma unroll
        for (int j = 0; j < 4; j++)
#pragma unroll
            for (int e = 0; e < 4; e++) acc[i][j][e] = 0.f;

    const int kIters = K / 64;

    auto issue = [&](int it) {
        const uint32_t soff = (uint32_t)(it % STAGES) * (2 * TILEB);
        const long kh = (long)it * 64 + ldc * 8;
#pragma unroll
        for (int pass = 0; pass < 4; pass++) {
            int row = ldr + pass * 32;
            uint32_t pc = (uint32_t)((ldc ^ (row & 7)) * 16);
            uint32_t sa = sb + soff + row * 128 + pc;
            const __half* ga = A + (long)(row0 + row) * K + kh;
            int sza = (row0 + row < M) ? 16 : 0;
            CP_ASYNC(sa, ga, sza);
            uint32_t sbb = sb + soff + TILEB + row * 128 + pc;
            const __half* gb = Bm + (long)(col0 + row) * K + kh;
            int szb = (col0 + row < N) ? 16 : 0;
            CP_ASYNC(sbb, gb, szb);
        }
        CP_COMMIT();
    };

    issue(0);
    issue(1);

    const int arow = ((lane >> 3) & 1) * 8 + (lane & 7);
    const int chi  = lane >> 4;

    for (int it = 0; it < kIters; ++it) {
        CP_WAIT1();
        __syncthreads();
        if (it + 2 < kIters) issue(it + 2);
        else CP_COMMIT();

        const uint32_t base = sb + (uint32_t)(it % STAGES) * (2 * TILEB);

#pragma unroll
        for (int s = 0; s < 4; s++) {
            const int ch = 2 * s + chi;
            uint32_t afr[4][4], bfr[2][4];
#pragma unroll
            for (int im = 0; im < 4; im++) {
                int row = wm * 64 + im * 16 + arow;
                uint32_t addr = base + row * 128 + ((ch ^ (row & 7)) * 16);
                LDSM_X4(afr[im], addr);
            }
#pragma unroll
            for (int jb = 0; jb < 2; jb++) {
                int rowb = wn * 32 + jb * 16 + arow;
                uint32_t addr = base + TILEB + rowb * 128 + ((ch ^ (rowb & 7)) * 16);
                LDSM_X4(bfr[jb], addr);
            }
#pragma unroll
            for (int im = 0; im < 4; im++) {
                mma_f16(acc[im][0], afr[im], bfr[0][0], bfr[0][2]);
                mma_f16(acc[im][1], afr[im], bfr[0][1], bfr[0][3]);
                mma_f16(acc[im][2], afr[im], bfr[1][0], bfr[1][2]);
                mma_f16(acc[im][3], afr[im], bfr[1][1], bfr[1][3]);
            }
        }
    }
    CP_WAIT0();

    // ---------------- vectorized epilogue (pairs n, n+1) ----------------
    const int rq = lane >> 2;
    const int c  = lane & 3;
#pragma unroll
    for (int im = 0; im < 4; im++) {
        const int m0 = row0 + wm * 64 + im * 16 + rq;
#pragma unroll
        for (int jn = 0; jn < 4; jn++) {
            const int n0 = col0 + wn * 32 + jn * 8 + c * 2;
            if (n0 >= N) continue;
#pragma unroll
            for (int hh = 0; hh < 2; hh++) {
                const int m = m0 + hh * 8;
                if (m >= M) continue;
                const float v0 = acc[im][jn][hh * 2];
                const float v1 = acc[im][jn][hh * 2 + 1];
                if constexpr (MODE == 1) {
                    int which = n0 >> 9;
                    int nn = n0 & 511;
                    const float* bp =
                        (which == 0) ? bias : ((which == 1) ? res : rowadd);
                    float2 bv = *(const float2*)(bp + nn);
                    int b = m / SEQ_, s = m - b * SEQ_;
                    int h = nn >> 6, dh = nn & 63;
                    *(__half2*)(Ch + (long)which * QKVOFF +
                                (((long)b * H_ + h) * SEQ_ + s) * DH_ + dh) =
                        __floats2half2_rn(v0 + bv.x, v1 + bv.y);
                } else if constexpr (MODE == 5) {
                    long idx = (long)m * N + n0;
                    float2 bv = *(const float2*)(bias + n0);
                    float2 rv = *(const float2*)(res + idx);
                    *(float2*)(C + idx) =
                        make_float2(v0 + bv.x + rv.x, v1 + bv.y + rv.y);
                } else if constexpr (MODE == 6) {
                    float2 bv = *(const float2*)(bias + n0);
                    *(__half2*)(Ch + (long)m * N + n0) = __floats2half2_rn(
                        gelu_exact(v0 + bv.x), gelu_exact(v1 + bv.y));
                } else if constexpr (MODE == 7) {
                    int b = m / NTOK_, p = m - b * NTOK_;
                    float2 rv = *(const float2*)(rowadd + (long)p * D_ + n0);
                    float f0 = v0 + rv.x, f1 = v1 + rv.y;
                    long idx = ((long)(b * SEQ_ + 1 + p)) * D_ + n0;
                    *(float2*)(C + idx) = make_float2(f0, f1);
                    *(__half2*)(Ch + idx) = __floats2half2_rn(f0, f1);
                }
            }
        }
    }
}

// ---------------- tensor-core flash attention (fp16 mma, fp32 softmax) -------
// 128 q-rows per block, 8 warps (16 rows each); K/V/mask cp.async 3-slot ring.
// dyn smem: Q 16K | K 3x8K | V 3x8K | mask 3x256B = 66304 B.
#define FQ_OFF 0
#define FK_OFF 16384
#define FV_OFF 40960
#define FM_OFF 65536
#define FSMEM  66304
#define NKV 15

__global__ __launch_bounds__(256, 2) void flashm_k(
    const __half* __restrict__ qg, const __half* __restrict__ kg,
    const __half* __restrict__ vg, __half* __restrict__ ctx,
    const int* __restrict__ mask, float scale)
{
    extern __shared__ char smraw[];
    const uint32_t sb = smem_u32(smraw);
    const int tid = threadIdx.x;
    const int lane = tid & 31;
    const int w = tid >> 5;            // 0..7
    const int z = blockIdx.y;
    const int b = z >> 3;
    const int h = z & 7;
    const int q0 = blockIdx.x * 128;
    const long base = (long)z * SEQ_ * DH_;
    const int mbase = b * SEQ_;

    const int arow = ((lane >> 3) & 1) * 8 + (lane & 7);
    const int chi  = lane >> 4;
    const int rq = lane >> 2;
    const int c  = lane & 3;

    // ---- Q load: 128 rows x 8 chunks = 1024 cp.asyncs ----
#pragma unroll
    for (int p = 0; p < 4; p++) {
        int idx = tid + p * 256;
        int row = idx >> 3, cc = idx & 7;
        uint32_t dst = sb + FQ_OFF + row * 128 + ((cc ^ (row & 7)) * 16);
        const __half* src = qg + base + (long)(q0 + row) * DH_ + cc * 8;
        CP_ASYNC(dst, src, (q0 + row < SEQ_) ? 16 : 0);
    }
    CP_COMMIT();

    auto issue_kv = [&](int t) {
        const int slot = t % 3;
        const uint32_t ko = sb + FK_OFF + slot * 8192;
        const uint32_t vo = sb + FV_OFF + slot * 8192;
#pragma unroll
        for (int p = 0; p < 2; p++) {
            int idx = tid + p * 256;
            int row = idx >> 3, cc = idx & 7;
            uint32_t pc = (uint32_t)((cc ^ (row & 7)) * 16);
            int s = t * 64 + row;
            int sz = (s < SEQ_) ? 16 : 0;
            CP_ASYNC(ko + row * 128 + pc, kg + base + (long)s * DH_ + cc * 8, sz);
            CP_ASYNC(vo + row * 128 + pc, vg + base + (long)s * DH_ + cc * 8, sz);
        }
        if (tid < 16) {
            int rem = SEQ_ - (t * 64 + tid * 4);
            int sz = rem >= 4 ? 16 : (rem > 0 ? rem * 4 : 0);
            CP_ASYNC(sb + FM_OFF + slot * 256 + tid * 16,
                     mask + mbase + t * 64 + tid * 4, sz);
        }
        CP_COMMIT();
    };
    issue_kv(0);
    issue_kv(1);

    CP_WAIT2();
    __syncthreads();
    uint32_t aq[4][4];
#pragma unroll
    for (int s = 0; s < 4; s++) {
        int row = w * 16 + arow;
        int ch = 2 * s + chi;
        LDSM_X4(aq[s], sb + FQ_OFF + row * 128 + ((ch ^ (row & 7)) * 16));
    }

    float m_lo = -1e30f, m_hi = -1e30f, l_lo = 0.f, l_hi = 0.f;
    float o[8][4];
#pragma unroll
    for (int nt = 0; nt < 8; nt++)
#pragma unroll
        for (int e = 0; e < 4; e++) o[nt][e] = 0.f;

    for (int t = 0; t < NKV; t++) {
        CP_WAIT1();
        __syncthreads();
        if (t + 2 < NKV) issue_kv(t + 2);
        else CP_COMMIT();

        const int slot = t % 3;
        const uint32_t kb = sb + FK_OFF + slot * 8192;
        const uint32_t vb = sb + FV_OFF + slot * 8192;
        const int* msk = (const int*)(smraw + FM_OFF + slot * 256);

        float sc[8][4];
#pragma unroll
        for (int j = 0; j < 8; j++)
#pragma unroll
            for (int e = 0; e < 4; e++) sc[j][e] = 0.f;
#pragma unroll
        for (int s = 0; s < 4; s++) {
            const int ch = 2 * s + chi;
#pragma unroll
            for (int jb = 0; jb < 4; jb++) {
                int rowb = jb * 16 + arow;
                uint32_t bk[4];
                LDSM_X4(bk, kb + rowb * 128 + ((ch ^ (rowb & 7)) * 16));
                mma_f16(sc[2 * jb],     aq[s], bk[0], bk[2]);
                mma_f16(sc[2 * jb + 1], aq[s], bk[1], bk[3]);
            }
        }

#pragma unroll
        for (int j = 0; j < 8; j++) {
            int col0 = j * 8 + 2 * c;
            bool ok0 = msk[col0] != 0;
            bool ok1 = msk[col0 + 1] != 0;
            sc[j][0] = ok0 ? sc[j][0] * scale : -1e9f;
            sc[j][1] = ok1 ? sc[j][1] * scale : -1e9f;
            sc[j][2] = ok0 ? sc[j][2] * scale : -1e9f;
            sc[j][3] = ok1 ? sc[j][3] * scale : -1e9f;
        }

        float rm_lo = -1e30f, rm_hi = -1e30f;
#pragma unroll
        for (int j = 0; j < 8; j++) {
            rm_lo = fmaxf(rm_lo, fmaxf(sc[j][0], sc[j][1]));
            rm_hi = fmaxf(rm_hi, fmaxf(sc[j][2], sc[j][3]));
        }
        rm_lo = fmaxf(rm_lo, __shfl_xor_sync(0xffffffffu, rm_lo, 1));
        rm_lo = fmaxf(rm_lo, __shfl_xor_sync(0xffffffffu, rm_lo, 2));
        rm_hi = fmaxf(rm_hi, __shfl_xor_sync(0xffffffffu, rm_hi, 1));
        rm_hi = fmaxf(rm_hi, __shfl_xor_sync(0xffffffffu, rm_hi, 2));

        float mn_lo = fmaxf(m_lo, rm_lo), mn_hi = fmaxf(m_hi, rm_hi);
        float corr_lo = expf(m_lo - mn_lo), corr_hi = expf(m_hi - mn_hi);
        m_lo = mn_lo; m_hi = mn_hi;

        uint32_t ap[4][4];
        float sum_lo = 0.f, sum_hi = 0.f;
#pragma unroll
        for (int j = 0; j < 8; j++) {
            float p0 = expf(sc[j][0] - m_lo);
            float p1 = expf(sc[j][1] - m_lo);
            float p2 = expf(sc[j][2] - m_hi);
            float p3 = expf(sc[j][3] - m_hi);
            sum_lo += p0 + p1;
            sum_hi += p2 + p3;
            int s = j >> 1;
            if ((j & 1) == 0) {
                ap[s][0] = packh2(p0, p1);
                ap[s][1] = packh2(p2, p3);
            } else {
                ap[s][2] = packh2(p0, p1);
                ap[s][3] = packh2(p2, p3);
            }
        }
        sum_lo += __shfl_xor_sync(0xffffffffu, sum_lo, 1);
        sum_lo += __shfl_xor_sync(0xffffffffu, sum_lo, 2);
        sum_hi += __shfl_xor_sync(0xffffffffu, sum_hi, 1);
        sum_hi += __shfl_xor_sync(0xffffffffu, sum_hi, 2);
        l_lo = l_lo * corr_lo + sum_lo;
        l_hi = l_hi * corr_hi + sum_hi;
#pragma unroll
        for (int nt = 0; nt < 8; nt++) {
            o[nt][0] *= corr_lo; o[nt][1] *= corr_lo;
            o[nt][2] *= corr_hi; o[nt][3] *= corr_hi;
        }

#pragma unroll
        for (int s = 0; s < 4; s++) {
#pragma unroll
            for (int g = 0; g < 4; g++) {
                int rowv = s * 16 + arow;
                int ch = 2 * g + chi;
                uint32_t bv[4];
                LDSM_X4_T(bv, vb + rowv * 128 + ((ch ^ (rowv & 7)) * 16));
                mma_f16(o[2 * g],     ap[s], bv[0], bv[1]);
                mma_f16(o[2 * g + 1], ap[s], bv[2], bv[3]);
            }
        }
    }
    CP_WAIT0();

    const float inv_lo = 1.f / l_lo;
    const float inv_hi = 1.f / l_hi;
    const int r_lo = q0 + w * 16 + rq;
    const int r_hi = r_lo + 8;
#pragma unroll
    for (int nt = 0; nt < 8; nt++) {
        int col = h * DH_ + nt * 8 + 2 * c;
        if (r_lo < SEQ_) {
            __half2 hv = __floats2half2_rn(o[nt][0] * inv_lo, o[nt][1] * inv_lo);
            *(__half2*)(ctx + ((long)(b * SEQ_ + r_lo)) * D_ + col) = hv;
        }
        if (r_hi < SEQ_) {
            __half2 hv = __floats2half2_rn(o[nt][2] * inv_hi, o[nt][3] * inv_hi);
            *(__half2*)(ctx + ((long)(b * SEQ_ + r_hi)) * D_ + col) = hv;
        }
    }
}

// ---------------- fused feature transpose -> half ----------------------------
__global__ void transpose_all_k(const float* __restrict__ f0,
                                const float* __restrict__ f1,
                                const float* __restrict__ f2,
                                __half* __restrict__ Aout)
{
    __shared__ float tile[32][33];
    const int bx = blockIdx.x;
    const float* feat;
    int HW, tokoff, hw0;
    if (bx < 24)      { feat = f0; HW = 768; tokoff = 0;   hw0 = bx * 32; }
    else if (bx < 28) { feat = f1; HW = 108; tokoff = 768; hw0 = (bx - 24) * 32; }
    else              { feat = f2; HW = 35;  tokoff = 876; hw0 = (bx - 28) * 32; }

    const int b = blockIdx.z;
    const int c0 = blockIdx.y * 32;
    const int tx = threadIdx.x, ty = threadIdx.y;

    const float* fb = feat + ((long)b * CIN_ + c0) * HW;
#pragma unroll
    for (int i = ty; i < 32; i += 8) {
        int hw = hw0 + tx;
        tile[i][tx] = (hw < HW) ? fb[(long)i * HW + hw] : 0.f;
    }
    __syncthreads();
#pragma unroll
    for (int i = ty; i < 32; i += 8) {
        int hw = hw0 + i;
        if (hw < HW)
            Aout[((long)(b * NTOK_ + tokoff + hw)) * CIN_ + c0 + tx] =
                __float2half(tile[tx][i]);
    }
}

__global__ void addvec_k(const float* __restrict__ conv_b,
                         const float* __restrict__ org_emb,
                         const float* __restrict__ r1_emb,
                         const float* __restrict__ r2_emb,
                         const float* __restrict__ pos_emb,
                         float* __restrict__ addv)
{
    int p = blockIdx.x;
    int d = threadIdx.x;
    int ti, tj;
    const float* emb;
    if (p < 768) {
        int h = p / 32, w = p - h * 32;
        ti = h * 10 / 24; tj = w * 10 / 32; emb = org_emb;
    } else if (p < 876) {
        int pp = p - 768;
        int h = pp / 12, w = pp - h * 12;
        ti = h * 10 / 9; tj = w * 10 / 12; emb = r1_emb;
    } else {
        int pp = p - 876;
        int h = pp / 7, w = pp - h * 7;
        ti = h * 10 / 5; tj = w * 10 / 7; emb = r2_emb;
    }
    addv[(long)p * D_ + d] = conv_b[d] + emb[d] + pos_emb[((long)ti * 10 + tj) * D_ + d];
}

__global__ void cls_k(const float* __restrict__ cls_token,
                      float* __restrict__ x, __half* __restrict__ xh)
{
    int b = blockIdx.x, d = threadIdx.x;
    float v = cls_token[d];
    x[((long)b * SEQ_) * D_ + d] = v;
    xh[((long)b * SEQ_) * D_ + d] = __float2half(v);
}

// ---------------- gather cls rows into compact [B, D] buffers ---------------
__global__ void gather_cls_k(const __half* __restrict__ ctxh,
                             const float* __restrict__ x,
                             __half* __restrict__ c8h,
                             float* __restrict__ x8)
{
    int b = blockIdx.x, tid = threadIdx.x;
#pragma unroll
    for (int p = 0; p < 2; p++) {
        int d = tid + p * 256;
        c8h[(long)b * D_ + d] = ctxh[((long)b * SEQ_) * D_ + d];
        x8[(long)b * D_ + d]  = x[((long)b * SEQ_) * D_ + d];
    }
}

// ---------------- warp-per-row layernorm --------------------------------------
__global__ void ln_w(const float* __restrict__ in, float* __restrict__ out,
                     __half* __restrict__ outh,
                     const float* __restrict__ g, const float* __restrict__ bb)
{
    const int w = threadIdx.x >> 5, lane = threadIdx.x & 31;
    const long t = (long)blockIdx.x * 8 + w;
    const float* x = in + t * D_;

    float4 v[4];
    float s = 0.f;
#pragma unroll
    for (int i = 0; i < 4; i++) {
        v[i] = *(const float4*)(x + lane * 4 + i * 128);
        s += (v[i].x + v[i].y) + (v[i].z + v[i].w);
    }
#pragma unroll
    for (int o = 16; o > 0; o >>= 1) s += __shfl_xor_sync(0xffffffffu, s, o);
    const float mean = s * (1.f / D_);

    float var = 0.f;
#pragma unroll
    for (int i = 0; i < 4; i++) {
        float dx = v[i].x - mean, dy = v[i].y - mean;
        float dz = v[i].z - mean, dw = v[i].w - mean;
        var += (dx * dx + dy * dy) + (dz * dz + dw * dw);
    }
#pragma unroll
    for (int o = 16; o > 0; o >>= 1) var += __shfl_xor_sync(0xffffffffu, var, o);
    const float rstd = rsqrtf(var * (1.f / D_) + 1e-6f);

    float* o_ = out + t * D_;
    __half* oh = outh + t * D_;
#pragma unroll
    for (int i = 0; i < 4; i++) {
        int d = lane * 4 + i * 128;
        float4 gv = *(const float4*)(g + d);
        float4 bv = *(const float4*)(bb + d);
        float4 r;
        r.x = (v[i].x - mean) * rstd * gv.x + bv.x;
        r.y = (v[i].y - mean) * rstd * gv.y + bv.y;
        r.z = (v[i].z - mean) * rstd * gv.z + bv.z;
        r.w = (v[i].w - mean) * rstd * gv.w + bv.w;
        *(float4*)(o_ + d) = r;
        __half2 h0 = __floats2half2_rn(r.x, r.y);
        __half2 h1 = __floats2half2_rn(r.z, r.w);
        *(uint2*)(oh + d) = make_uint2(*(uint32_t*)&h0, *(uint32_t*)&h1);
    }
}

// ---------------- MLP head on compact cls rows --------------------------------
__global__ void head_k(const float* __restrict__ x8,
                       const float* __restrict__ w1,
                       const float* __restrict__ w2,
                       float* __restrict__ out)
{
    int b = blockIdx.x;
    int tid = threadIdx.x;
    __shared__ float cls[D_];
    __shared__ float red[256];
    for (int i = tid; i < D_; i += 256)
        cls[i] = x8[(long)b * D_ + i];
    __syncthreads();

    float partial = 0.f;
    for (int j = tid; j < DMLP_; j += 256) {
        const float* w = w1 + (long)j * D_;
        float s = 0.f;
#pragma unroll 8
        for (int k = 0; k < D_; k++) s += cls[k] * w[k];
        partial += gelu_exact(s) * w2[j];
    }
    red[tid] = partial; __syncthreads();
    for (int k = 128; k > 0; k >>= 1) {
        if (tid < k) red[tid] += red[tid + k];
        __syncthreads();
    }
    if (tid == 0) out[b] = red[0];
}

// =============================================================================
extern "C" void kernel_launch(void* const* d_in, const int* in_sizes, int n_in,
                              void* d_out, int out_size)
{
    const float* feat_org = (const float*)d_in[0];
    const float* feat_r1  = (const float*)d_in[1];
    const float* feat_r2  = (const float*)d_in[2];
    const float* conv_w   = (const float*)d_in[3];
    const float* conv_b   = (const float*)d_in[4];
    const float* org_emb  = (const float*)d_in[5];
    const float* r1_emb   = (const float*)d_in[6];
    const float* r2_emb   = (const float*)d_in[7];
    const float* pos_emb  = (const float*)d_in[8];
    const float* cls_tok  = (const float*)d_in[9];
    const float* Wq = (const float*)d_in[10];
    const float* bq = (const float*)d_in[11];
    const float* Wk = (const float*)d_in[12];
    const float* bk = (const float*)d_in[13];
    const float* Wv = (const float*)d_in[14];
    const float* bv = (const float*)d_in[15];
    const float* Wo = (const float*)d_in[16];
    const float* bo = (const float*)d_in[17];
    const float* ln1g = (const float*)d_in[18];
    const float* ln1b = (const float*)d_in[19];
    const float* w1 = (const float*)d_in[20];
    const float* b1 = (const float*)d_in[21];
    const float* w2 = (const float*)d_in[22];
    const float* b2 = (const float*)d_in[23];
    const float* ln2g = (const float*)d_in[24];
    const float* ln2b = (const float*)d_in[25];
    const float* pw1 = (const float*)d_in[26];
    const float* pw2 = (const float*)d_in[27];
    const int*   mask = (const int*)d_in[28];
    float* out = (float*)d_out;

    __half *Ah, *xh, *qkvh, *ctxh, *ffh, *wqkv, *woh, *w1h, *w2h, *cwh;
    __half *c8h, *x8h, *f8h;
    float *addv, *x, *tmp, *x8, *t8;
    cudaGetSymbolAddress((void**)&Ah, g_Ah);
    cudaGetSymbolAddress((void**)&addv, g_add);
    cudaGetSymbolAddress((void**)&x, g_x);
    cudaGetSymbolAddress((void**)&xh, g_xh);
    cudaGetSymbolAddress((void**)&tmp, g_tmp);
    cudaGetSymbolAddress((void**)&qkvh, g_qkvh);
    cudaGetSymbolAddress((void**)&ctxh, g_ctxh);
    cudaGetSymbolAddress((void**)&ffh, g_ffh);
    cudaGetSymbolAddress((void**)&wqkv, g_wqkv);
    cudaGetSymbolAddress((void**)&woh, g_woh);
    cudaGetSymbolAddress((void**)&w1h, g_w1h);
    cudaGetSymbolAddress((void**)&w2h, g_w2h);
    cudaGetSymbolAddress((void**)&cwh, g_cwh);
    cudaGetSymbolAddress((void**)&c8h, g_c8h);
    cudaGetSymbolAddress((void**)&x8, g_x8);
    cudaGetSymbolAddress((void**)&t8, g_t8);
    cudaGetSymbolAddress((void**)&x8h, g_x8h);
    cudaGetSymbolAddress((void**)&f8h, g_f8h);

    cudaFuncSetAttribute(flashm_k, cudaFuncAttributeMaxDynamicSharedMemorySize, FSMEM);
    cudaFuncSetAttribute(gemm_cp<1>, cudaFuncAttributeMaxDynamicSharedMemorySize, GSMEM);
    cudaFuncSetAttribute(gemm_cp<5>, cudaFuncAttributeMaxDynamicSharedMemorySize, GSMEM);
    cudaFuncSetAttribute(gemm_cp<6>, cudaFuncAttributeMaxDynamicSharedMemorySize, GSMEM);
    cudaFuncSetAttribute(gemm_cp<7>, cudaFuncAttributeMaxDynamicSharedMemorySize, GSMEM);

    // launch order: #4 = embed GEMM so the ncu capture window profiles gemm_cp
    transpose_all_k<<<dim3(30, CIN_ / 32, B_), dim3(32, 8)>>>(feat_org, feat_r1,
                                                              feat_r2, Ah);
    addvec_k<<<NTOK_, D_>>>(conv_b, org_emb, r1_emb, r2_emb, pos_emb, addv);
    stage_k<<<2048, 256>>>(conv_w, Wo, w1, w2, Wq, Wk, Wv,
                           cwh, woh, w1h, w2h, wqkv);
    gemm_cp<7><<<dim3(4, 57), 256, GSMEM>>>(Ah, cwh, x, xh, B_ * NTOK_, D_, CIN_,
                                            nullptr, nullptr, addv);
    cls_k<<<B_, D_>>>(cls_tok, x, xh);

    const float scale = 0.125f;  // 1/sqrt(64)
    for (int i = 0; i < L_ - 1; i++) {
        gemm_cp<1><<<dim3(12, 57), 256, GSMEM>>>(xh, wqkv + (long)i * 3 * D_ * D_,
                                                 nullptr, qkvh, B_ * SEQ_, 3 * D_, D_,
                                                 bq + i * D_, bk + i * D_, bv + i * D_);

        flashm_k<<<dim3(8, B_ * H_), 256, FSMEM>>>(
            qkvh, qkvh + QKVOFF, qkvh + 2 * QKVOFF, ctxh, mask, scale);

        gemm_cp<5><<<dim3(4, 57), 256, GSMEM>>>(ctxh, woh + (long)i * D_ * D_,
                                                tmp, nullptr, B_ * SEQ_, D_, D_,
                                                bo + i * D_, x, nullptr);
        ln_w<<<B_ * SEQ_ / 8, 256>>>(tmp, x, xh, ln1g + i * D_, ln1b + i * D_);

        gemm_cp<6><<<dim3(16, 57), 256, GSMEM>>>(xh, w1h + (long)i * DFF_ * D_,
                                                 nullptr, ffh, B_ * SEQ_, DFF_, D_,
                                                 b1 + i * DFF_, nullptr, nullptr);
        gemm_cp<5><<<dim3(4, 57), 256, GSMEM>>>(ffh, w2h + (long)i * D_ * DFF_,
                                                tmp, nullptr, B_ * SEQ_, D_, DFF_,
                                                b2 + i * D_, x, nullptr);
        ln_w<<<B_ * SEQ_ / 8, 256>>>(tmp, x, xh, ln2g + i * D_, ln2b + i * D_);
    }

    // ---- last layer: only cls tokens matter after attention ----
    {
        const int i = L_ - 1;
        gemm_cp<1><<<dim3(12, 57), 256, GSMEM>>>(xh, wqkv + (long)i * 3 * D_ * D_,
                                                 nullptr, qkvh, B_ * SEQ_, 3 * D_, D_,
                                                 bq + i * D_, bk + i * D_, bv + i * D_);
        flashm_k<<<dim3(1, B_ * H_), 256, FSMEM>>>(
            qkvh, qkvh + QKVOFF, qkvh + 2 * QKVOFF, ctxh, mask, scale);

        gather_cls_k<<<B_, 256>>>(ctxh, x, c8h, x8);

        gemm_cp<5><<<dim3(4, 1), 256, GSMEM>>>(c8h, woh + (long)i * D_ * D_,
                                               t8, nullptr, B_, D_, D_,
                                               bo + i * D_, x8, nullptr);
        ln_w<<<1, 256>>>(t8, x8, x8h, ln1g + i * D_, ln1b + i * D_);

        gemm_cp<6><<<dim3(16, 1), 256, GSMEM>>>(x8h, w1h + (long)i * DFF_ * D_,
                                                nullptr, f8h, B_, DFF_, D_,
                                                b1 + i * DFF_, nullptr, nullptr);
        gemm_cp<5><<<dim3(4, 1), 256, GSMEM>>>(f8h, w2h + (long)i * D_ * DFF_,
                                               t8, nullptr, B_, D_, DFF_,
                                               b2 + i * D_, x8, nullptr);
        ln_w<<<1, 256>>>(t8, x8, x8h, ln2g + i * D_, ln2b + i * D_);
    }

    head_k<<<B_, 256>>>(x8, pw1, pw2, out);
}

// round 14
// speedup vs baseline: 1.0974x; 1.0974x over previous
#include <cuda_runtime.h>
#include <cuda_fp16.h>
#include <math.h>
#include <stdint.h>

#define B_    8
#define D_    512
#define H_    8
#define DH_   64
#define L_    6
#define DFF_  2048
#define CIN_  2048
#define SEQ_  912
#define NTOK_ 911
#define DMLP_ 1024
#define QKVOFF ((long)B_ * SEQ_ * D_)

// ---------------- scratch (static device globals; allocation-free) ----------
__device__ __align__(16) __half g_Ah[(size_t)B_ * NTOK_ * CIN_];
__device__ __align__(16) float  g_add[(size_t)NTOK_ * D_];
__device__ __align__(16) float  g_x[(size_t)B_ * SEQ_ * D_];
__device__ __align__(16) __half g_xh[(size_t)B_ * SEQ_ * D_];
__device__ __align__(16) float  g_tmp[(size_t)B_ * SEQ_ * D_];
__device__ __align__(16) __half g_qkvh[3 * (size_t)B_ * SEQ_ * D_];
__device__ __align__(16) __half g_ctxh[(size_t)B_ * SEQ_ * D_];
__device__ __align__(16) __half g_ffh[(size_t)B_ * SEQ_ * DFF_];
__device__ __align__(16) __half g_wqkv[(size_t)L_ * 3 * D_ * D_];
__device__ __align__(16) __half g_woh[(size_t)L_ * D_ * D_];
__device__ __align__(16) __half g_w1h[(size_t)L_ * DFF_ * D_];
__device__ __align__(16) __half g_w2h[(size_t)L_ * D_ * DFF_];
__device__ __align__(16) __half g_cwh[(size_t)D_ * CIN_];
// last-layer compact cls-path buffers
__device__ __align__(16) __half g_c8h[(size_t)B_ * D_];
__device__ __align__(16) float  g_x8[(size_t)B_ * D_];
__device__ __align__(16) float  g_t8[(size_t)B_ * D_];
__device__ __align__(16) __half g_x8h[(size_t)B_ * D_];
__device__ __align__(16) __half g_f8h[(size_t)B_ * DFF_];

__device__ __forceinline__ float gelu_exact(float x) {
    return 0.5f * x * (1.0f + erff(x * 0.70710678118654752f));
}
__device__ __forceinline__ uint32_t smem_u32(const void* p) {
    uint32_t a;
    asm("{ .reg .u64 t; cvta.to.shared.u64 t, %1; cvt.u32.u64 %0, t; }"
        : "=r"(a) : "l"(p));
    return a;
}
__device__ __forceinline__ uint32_t packh2(float x, float y) {
    __half2 h = __floats2half2_rn(x, y);
    return *(uint32_t*)&h;
}
__device__ __forceinline__ void mma_f16(float c[4], const uint32_t a[4],
                                        uint32_t b0, uint32_t b1) {
    asm volatile(
        "mma.sync.aligned.m16n8k16.row.col.f32.f16.f16.f32 "
        "{%0,%1,%2,%3}, {%4,%5,%6,%7}, {%8,%9}, {%0,%1,%2,%3};"
        : "+f"(c[0]), "+f"(c[1]), "+f"(c[2]), "+f"(c[3])
        : "r"(a[0]), "r"(a[1]), "r"(a[2]), "r"(a[3]), "r"(b0), "r"(b1));
}
#define LDSM_X4(r, addr) \
    asm volatile("ldmatrix.sync.aligned.m8n8.x4.shared.b16 {%0,%1,%2,%3}, [%4];" \
        : "=r"((r)[0]), "=r"((r)[1]), "=r"((r)[2]), "=r"((r)[3]) : "r"(addr))
#define LDSM_X4_T(r, addr) \
    asm volatile("ldmatrix.sync.aligned.m8n8.x4.trans.shared.b16 {%0,%1,%2,%3}, [%4];" \
        : "=r"((r)[0]), "=r"((r)[1]), "=r"((r)[2]), "=r"((r)[3]) : "r"(addr))
#define CP_ASYNC(dst, src, sz) \
    asm volatile("cp.async.cg.shared.global [%0], [%1], 16, %2;" \
                 :: "r"(dst), "l"(src), "r"(sz) : "memory")
#define CP_COMMIT() asm volatile("cp.async.commit_group;" ::: "memory")
#define CP_WAIT2()  asm volatile("cp.async.wait_group 2;" ::: "memory")
#define CP_WAIT1()  asm volatile("cp.async.wait_group 1;" ::: "memory")
#define CP_WAIT0()  asm volatile("cp.async.wait_group 0;" ::: "memory")

// ---------------- single staging kernel: all weights -> half -----------------
__global__ void stage_k(const float* __restrict__ conv_w,
                        const float* __restrict__ Wo,
                        const float* __restrict__ w1,
                        const float* __restrict__ w2,
                        const float* __restrict__ Wq,
                        const float* __restrict__ Wk,
                        const float* __restrict__ Wv,
                        __half* __restrict__ cwh, __half* __restrict__ woh,
                        __half* __restrict__ w1h, __half* __restrict__ w2h,
                        __half* __restrict__ wqkv)
{
    const long n0 = (long)D_ * CIN_ / 4;
    const long n1 = (long)L_ * D_ * D_ / 4;
    const long n2 = (long)L_ * DFF_ * D_ / 4;
    const long n3 = (long)L_ * D_ * DFF_ / 4;
    const long n4 = (long)L_ * 3 * D_ * D_ / 4;
    const long total = n0 + n1 + n2 + n3 + n4;
    const long per = (long)D_ * D_ / 4;

    for (long i = (long)blockIdx.x * blockDim.x + threadIdx.x; i < total;
         i += (long)gridDim.x * blockDim.x) {
        const float* src;
        __half* dst;
        long so, dd;
        if (i < n0)                { src = conv_w; dst = cwh; so = i; dd = i; }
        else if (i < n0 + n1)      { src = Wo; dst = woh; so = i - n0; dd = so; }
        else if (i < n0 + n1 + n2) { src = w1; dst = w1h; so = i - n0 - n1; dd = so; }
        else if (i < n0 + n1 + n2 + n3) {
            src = w2; dst = w2h; so = i - n0 - n1 - n2; dd = so;
        } else {
            long r = i - n0 - n1 - n2 - n3;
            long l = r / (3 * per);
            long q = (r / per) % 3;
            long o = r % per;
            src = (q == 0 ? Wq : (q == 1 ? Wk : Wv));
            so = l * per + o;
            dst = wqkv; dd = r;
        }
        float4 v = *((const float4*)src + so);
        __half2* d = (__half2*)(dst + dd * 4);
        d[0] = __floats2half2_rn(v.x, v.y);
        d[1] = __floats2half2_rn(v.z, v.w);
    }
}

// ---------------- cp.async + ldmatrix FP16 GEMM: C = A(MxK)*B(NxK)^T ---------
// BM=128, BN templated (128: 2 CTA/SM; 64: 32-reg acc, 24KB stages, 3 CTA/SM).
#define STAGES 3
#define TILEA  16384
#define GSMEM_FOR(BN) (STAGES * (TILEA + (BN) * 128))

template <int BN, int MODE>
__global__ __launch_bounds__(256, (BN == 64) ? 3 : 2) void gemm_cp(
    const __half* __restrict__ A, const __half* __restrict__ Bm,
    float* __restrict__ C, __half* __restrict__ Ch, int M, int N, int K,
    const float* __restrict__ bias,
    const float* __restrict__ res,
    const float* __restrict__ rowadd)
{
    constexpr int NB16  = BN / 64;          // 16-col b-tiles per warp
    constexpr int WN    = BN / 4;           // warp col span
    constexpr int NT    = 2 * NB16;         // 8-col n-tiles per warp
    constexpr int TILEBB = BN * 128;
    constexpr int STAGEB = TILEA + TILEBB;
    constexpr int BPASS  = BN / 32;

    extern __shared__ char smraw[];
    const uint32_t sb = smem_u32(smraw);
    const int tid  = threadIdx.x;
    const int lane = tid & 31;
    const int wid  = tid >> 5;
    const int wm   = wid & 1;
    const int wn   = wid >> 1;
    const int row0 = blockIdx.y * 128;
    const int col0 = blockIdx.x * BN;

    const int ldr = tid >> 3;
    const int ldc = tid & 7;

    float acc[4][NT][4];
#pragma unroll
    for (int i = 0; i < 4; i++)
#pragma unroll
        for (int j = 0; j < NT; j++)
#pragma unroll
            for (int e = 0; e < 4; e++) acc[i][j][e] = 0.f;

    const int kIters = K / 64;

    auto issue = [&](int it) {
        const uint32_t soff = (uint32_t)(it % STAGES) * STAGEB;
        const long kh = (long)it * 64 + ldc * 8;
#pragma unroll
        for (int pass = 0; pass < 4; pass++) {
            int row = ldr + pass * 32;
            uint32_t pc = (uint32_t)((ldc ^ (row & 7)) * 16);
            uint32_t sa = sb + soff + row * 128 + pc;
            const __half* ga = A + (long)(row0 + row) * K + kh;
            int sza = (row0 + row < M) ? 16 : 0;
            CP_ASYNC(sa, ga, sza);
        }
#pragma unroll
        for (int pass = 0; pass < BPASS; pass++) {
            int row = ldr + pass * 32;
            uint32_t pc = (uint32_t)((ldc ^ (row & 7)) * 16);
            uint32_t sbb = sb + soff + TILEA + row * 128 + pc;
            const __half* gb = Bm + (long)(col0 + row) * K + kh;
            int szb = (col0 + row < N) ? 16 : 0;
            CP_ASYNC(sbb, gb, szb);
        }
        CP_COMMIT();
    };

    issue(0);
    issue(1);

    const int arow = ((lane >> 3) & 1) * 8 + (lane & 7);
    const int chi  = lane >> 4;

    for (int it = 0; it < kIters; ++it) {
        CP_WAIT1();
        __syncthreads();
        if (it + 2 < kIters) issue(it + 2);
        else CP_COMMIT();

        const uint32_t base = sb + (uint32_t)(it % STAGES) * STAGEB;

#pragma unroll
        for (int s = 0; s < 4; s++) {
            const int ch = 2 * s + chi;
            uint32_t afr[4][4], bfr[NB16][4];
#pragma unroll
            for (int im = 0; im < 4; im++) {
                int row = wm * 64 + im * 16 + arow;
                uint32_t addr = base + row * 128 + ((ch ^ (row & 7)) * 16);
                LDSM_X4(afr[im], addr);
            }
#pragma unroll
            for (int jb = 0; jb < NB16; jb++) {
                int rowb = wn * WN + jb * 16 + arow;
                uint32_t addr = base + TILEA + rowb * 128 + ((ch ^ (rowb & 7)) * 16);
                LDSM_X4(bfr[jb], addr);
            }
#pragma unroll
            for (int im = 0; im < 4; im++) {
#pragma unroll
                for (int jb = 0; jb < NB16; jb++) {
                    mma_f16(acc[im][2 * jb],     afr[im], bfr[jb][0], bfr[jb][2]);
                    mma_f16(acc[im][2 * jb + 1], afr[im], bfr[jb][1], bfr[jb][3]);
                }
            }
        }
    }
    CP_WAIT0();

    // ---------------- vectorized epilogue (pairs n, n+1) ----------------
    const int rq = lane >> 2;
    const int c  = lane & 3;
#pragma unroll
    for (int im = 0; im < 4; im++) {
        const int m0 = row0 + wm * 64 + im * 16 + rq;
#pragma unroll
        for (int jn = 0; jn < NT; jn++) {
            const int n0 = col0 + wn * WN + jn * 8 + c * 2;
            if (n0 >= N) continue;
#pragma unroll
            for (int hh = 0; hh < 2; hh++) {
                const int m = m0 + hh * 8;
                if (m >= M) continue;
                const float v0 = acc[im][jn][hh * 2];
                const float v1 = acc[im][jn][hh * 2 + 1];
                if constexpr (MODE == 1) {
                    int which = n0 >> 9;
                    int nn = n0 & 511;
                    const float* bp =
                        (which == 0) ? bias : ((which == 1) ? res : rowadd);
                    float2 bv = *(const float2*)(bp + nn);
                    int b = m / SEQ_, s = m - b * SEQ_;
                    int h = nn >> 6, dh = nn & 63;
                    *(__half2*)(Ch + (long)which * QKVOFF +
                                (((long)b * H_ + h) * SEQ_ + s) * DH_ + dh) =
                        __floats2half2_rn(v0 + bv.x, v1 + bv.y);
                } else if constexpr (MODE == 5) {
                    long idx = (long)m * N + n0;
                    float2 bv = *(const float2*)(bias + n0);
                    float2 rv = *(const float2*)(res + idx);
                    *(float2*)(C + idx) =
                        make_float2(v0 + bv.x + rv.x, v1 + bv.y + rv.y);
                } else if constexpr (MODE == 6) {
                    float2 bv = *(const float2*)(bias + n0);
                    *(__half2*)(Ch + (long)m * N + n0) = __floats2half2_rn(
                        gelu_exact(v0 + bv.x), gelu_exact(v1 + bv.y));
                } else if constexpr (MODE == 7) {
                    int b = m / NTOK_, p = m - b * NTOK_;
                    float2 rv = *(const float2*)(rowadd + (long)p * D_ + n0);
                    float f0 = v0 + rv.x, f1 = v1 + rv.y;
                    long idx = ((long)(b * SEQ_ + 1 + p)) * D_ + n0;
                    *(float2*)(C + idx) = make_float2(f0, f1);
                    *(__half2*)(Ch + idx) = __floats2half2_rn(f0, f1);
                }
            }
        }
    }
}

// ---------------- tensor-core flash attention (fp16 mma, fp32 softmax) -------
// R12 version: 64 q-rows, 128 threads, 4 warps; K/V/mask cp.async 3-slot ring.
#define FQ_OFF 0
#define FK_OFF 8192
#define FV_OFF 32768
#define FM_OFF 57344
#define FSMEM  58112
#define NKV 15

__global__ __launch_bounds__(128, 3) void flashm_k(
    const __half* __restrict__ qg, const __half* __restrict__ kg,
    const __half* __restrict__ vg, __half* __restrict__ ctx,
    const int* __restrict__ mask, float scale)
{
    extern __shared__ char smraw[];
    const uint32_t sb = smem_u32(smraw);
    const int tid = threadIdx.x;
    const int lane = tid & 31;
    const int w = tid >> 5;
    const int z = blockIdx.y;
    const int b = z >> 3;
    const int h = z & 7;
    const int q0 = blockIdx.x * 64;
    const long base = (long)z * SEQ_ * DH_;
    const int mbase = b * SEQ_;

    const int arow = ((lane >> 3) & 1) * 8 + (lane & 7);
    const int chi  = lane >> 4;
    const int rq = lane >> 2;
    const int c  = lane & 3;

#pragma unroll
    for (int p = 0; p < 4; p++) {
        int idx = tid + p * 128;
        int row = idx >> 3, cc = idx & 7;
        uint32_t dst = sb + FQ_OFF + row * 128 + ((cc ^ (row & 7)) * 16);
        const __half* src = qg + base + (long)(q0 + row) * DH_ + cc * 8;
        CP_ASYNC(dst, src, (q0 + row < SEQ_) ? 16 : 0);
    }
    CP_COMMIT();

    auto issue_kv = [&](int t) {
        const int slot = t % 3;
        const uint32_t ko = sb + FK_OFF + slot * 8192;
        const uint32_t vo = sb + FV_OFF + slot * 8192;
#pragma unroll
        for (int p = 0; p < 4; p++) {
            int idx = tid + p * 128;
            int row = idx >> 3, cc = idx & 7;
            uint32_t pc = (uint32_t)((cc ^ (row & 7)) * 16);
            int s = t * 64 + row;
            int sz = (s < SEQ_) ? 16 : 0;
            CP_ASYNC(ko + row * 128 + pc, kg + base + (long)s * DH_ + cc * 8, sz);
            CP_ASYNC(vo + row * 128 + pc, vg + base + (long)s * DH_ + cc * 8, sz);
        }
        if (tid < 16) {
            int rem = SEQ_ - (t * 64 + tid * 4);
            int sz = rem >= 4 ? 16 : (rem > 0 ? rem * 4 : 0);
            CP_ASYNC(sb + FM_OFF + slot * 256 + tid * 16,
                     mask + mbase + t * 64 + tid * 4, sz);
        }
        CP_COMMIT();
    };
    issue_kv(0);
    issue_kv(1);

    CP_WAIT2();
    __syncthreads();
    uint32_t aq[4][4];
#pragma unroll
    for (int s = 0; s < 4; s++) {
        int row = w * 16 + arow;
        int ch = 2 * s + chi;
        LDSM_X4(aq[s], sb + FQ_OFF + row * 128 + ((ch ^ (row & 7)) * 16));
    }

    float m_lo = -1e30f, m_hi = -1e30f, l_lo = 0.f, l_hi = 0.f;
    float o[8][4];
#pragma unroll
    for (int nt = 0; nt < 8; nt++)
#pragma unroll
        for (int e = 0; e < 4; e++) o[nt][e] = 0.f;

    for (int t = 0; t < NKV; t++) {
        CP_WAIT1();
        __syncthreads();
        if (t + 2 < NKV) issue_kv(t + 2);
        else CP_COMMIT();

        const int slot = t % 3;
        const uint32_t kb = sb + FK_OFF + slot * 8192;
        const uint32_t vb = sb + FV_OFF + slot * 8192;
        const int* msk = (const int*)(smraw + FM_OFF + slot * 256);

        float sc[8][4];
#pragma unroll
        for (int j = 0; j < 8; j++)
#pragma unroll
            for (int e = 0; e < 4; e++) sc[j][e] = 0.f;
#pragma unroll
        for (int s = 0; s < 4; s++) {
            const int ch = 2 * s + chi;
#pragma unroll
            for (int jb = 0; jb < 4; jb++) {
                int rowb = jb * 16 + arow;
                uint32_t bk[4];
                LDSM_X4(bk, kb + rowb * 128 + ((ch ^ (rowb & 7)) * 16));
                mma_f16(sc[2 * jb],     aq[s], bk[0], bk[2]);
                mma_f16(sc[2 * jb + 1], aq[s], bk[1], bk[3]);
            }
        }

#pragma unroll
        for (int j = 0; j < 8; j++) {
            int col0 = j * 8 + 2 * c;
            bool ok0 = msk[col0] != 0;
            bool ok1 = msk[col0 + 1] != 0;
            sc[j][0] = ok0 ? sc[j][0] * scale : -1e9f;
            sc[j][1] = ok1 ? sc[j][1] * scale : -1e9f;
            sc[j][2] = ok0 ? sc[j][2] * scale : -1e9f;
            sc[j][3] = ok1 ? sc[j][3] * scale : -1e9f;
        }

        float rm_lo = -1e30f, rm_hi = -1e30f;
#pragma unroll
        for (int j = 0; j < 8; j++) {
            rm_lo = fmaxf(rm_lo, fmaxf(sc[j][0], sc[j][1]));
            rm_hi = fmaxf(rm_hi, fmaxf(sc[j][2], sc[j][3]));
        }
        rm_lo = fmaxf(rm_lo, __shfl_xor_sync(0xffffffffu, rm_lo, 1));
        rm_lo = fmaxf(rm_lo, __shfl_xor_sync(0xffffffffu, rm_lo, 2));
        rm_hi = fmaxf(rm_hi, __shfl_xor_sync(0xffffffffu, rm_hi, 1));
        rm_hi = fmaxf(rm_hi, __shfl_xor_sync(0xffffffffu, rm_hi, 2));

        float mn_lo = fmaxf(m_lo, rm_lo), mn_hi = fmaxf(m_hi, rm_hi);
        float corr_lo = expf(m_lo - mn_lo), corr_hi = expf(m_hi - mn_hi);
        m_lo = mn_lo; m_hi = mn_hi;

        uint32_t ap[4][4];
        float sum_lo = 0.f, sum_hi = 0.f;
#pragma unroll
        for (int j = 0; j < 8; j++) {
            float p0 = expf(sc[j][0] - m_lo);
            float p1 = expf(sc[j][1] - m_lo);
            float p2 = expf(sc[j][2] - m_hi);
            float p3 = expf(sc[j][3] - m_hi);
            sum_lo += p0 + p1;
            sum_hi += p2 + p3;
            int s = j >> 1;
            if ((j & 1) == 0) {
                ap[s][0] = packh2(p0, p1);
                ap[s][1] = packh2(p2, p3);
            } else {
                ap[s][2] = packh2(p0, p1);
                ap[s][3] = packh2(p2, p3);
            }
        }
        sum_lo += __shfl_xor_sync(0xffffffffu, sum_lo, 1);
        sum_lo += __shfl_xor_sync(0xffffffffu, sum_lo, 2);
        sum_hi += __shfl_xor_sync(0xffffffffu, sum_hi, 1);
        sum_hi += __shfl_xor_sync(0xffffffffu, sum_hi, 2);
        l_lo = l_lo * corr_lo + sum_lo;
        l_hi = l_hi * corr_hi + sum_hi;
#pragma unroll
        for (int nt = 0; nt < 8; nt++) {
            o[nt][0] *= corr_lo; o[nt][1] *= corr_lo;
            o[nt][2] *= corr_hi; o[nt][3] *= corr_hi;
        }

#pragma unroll
        for (int s = 0; s < 4; s++) {
#pragma unroll
            for (int g = 0; g < 4; g++) {
                int rowv = s * 16 + arow;
                int ch = 2 * g + chi;
                uint32_t bv[4];
                LDSM_X4_T(bv, vb + rowv * 128 + ((ch ^ (rowv & 7)) * 16));
                mma_f16(o[2 * g],     ap[s], bv[0], bv[1]);
                mma_f16(o[2 * g + 1], ap[s], bv[2], bv[3]);
            }
        }
    }
    CP_WAIT0();

    const float inv_lo = 1.f / l_lo;
    const float inv_hi = 1.f / l_hi;
    const int r_lo = q0 + w * 16 + rq;
    const int r_hi = r_lo + 8;
#pragma unroll
    for (int nt = 0; nt < 8; nt++) {
        int col = h * DH_ + nt * 8 + 2 * c;
        if (r_lo < SEQ_) {
            __half2 hv = __floats2half2_rn(o[nt][0] * inv_lo, o[nt][1] * inv_lo);
            *(__half2*)(ctx + ((long)(b * SEQ_ + r_lo)) * D_ + col) = hv;
        }
        if (r_hi < SEQ_) {
            __half2 hv = __floats2half2_rn(o[nt][2] * inv_hi, o[nt][3] * inv_hi);
            *(__half2*)(ctx + ((long)(b * SEQ_ + r_hi)) * D_ + col) = hv;
        }
    }
}

// ---------------- fused feature transpose -> half ----------------------------
__global__ void transpose_all_k(const float* __restrict__ f0,
                                const float* __restrict__ f1,
                                const float* __restrict__ f2,
                                __half* __restrict__ Aout)
{
    __shared__ float tile[32][33];
    const int bx = blockIdx.x;
    const float* feat;
    int HW, tokoff, hw0;
    if (bx < 24)      { feat = f0; HW = 768; tokoff = 0;   hw0 = bx * 32; }
    else if (bx < 28) { feat = f1; HW = 108; tokoff = 768; hw0 = (bx - 24) * 32; }
    else              { feat = f2; HW = 35;  tokoff = 876; hw0 = (bx - 28) * 32; }

    const int b = blockIdx.z;
    const int c0 = blockIdx.y * 32;
    const int tx = threadIdx.x, ty = threadIdx.y;

    const float* fb = feat + ((long)b * CIN_ + c0) * HW;
#pragma unroll
    for (int i = ty; i < 32; i += 8) {
        int hw = hw0 + tx;
        tile[i][tx] = (hw < HW) ? fb[(long)i * HW + hw] : 0.f;
    }
    __syncthreads();
#pragma unroll
    for (int i = ty; i < 32; i += 8) {
        int hw = hw0 + i;
        if (hw < HW)
            Aout[((long)(b * NTOK_ + tokoff + hw)) * CIN_ + c0 + tx] =
                __float2half(tile[tx][i]);
    }
}

__global__ void addvec_k(const float* __restrict__ conv_b,
                         const float* __restrict__ org_emb,
                         const float* __restrict__ r1_emb,
                         const float* __restrict__ r2_emb,
                         const float* __restrict__ pos_emb,
                         float* __restrict__ addv)
{
    int p = blockIdx.x;
    int d = threadIdx.x;
    int ti, tj;
    const float* emb;
    if (p < 768) {
        int h = p / 32, w = p - h * 32;
        ti = h * 10 / 24; tj = w * 10 / 32; emb = org_emb;
    } else if (p < 876) {
        int pp = p - 768;
        int h = pp / 12, w = pp - h * 12;
        ti = h * 10 / 9; tj = w * 10 / 12; emb = r1_emb;
    } else {
        int pp = p - 876;
        int h = pp / 7, w = pp - h * 7;
        ti = h * 10 / 5; tj = w * 10 / 7; emb = r2_emb;
    }
    addv[(long)p * D_ + d] = conv_b[d] + emb[d] + pos_emb[((long)ti * 10 + tj) * D_ + d];
}

__global__ void cls_k(const float* __restrict__ cls_token,
                      float* __restrict__ x, __half* __restrict__ xh)
{
    int b = blockIdx.x, d = threadIdx.x;
    float v = cls_token[d];
    x[((long)b * SEQ_) * D_ + d] = v;
    xh[((long)b * SEQ_) * D_ + d] = __float2half(v);
}

// ---------------- gather cls rows into compact [B, D] buffers ---------------
__global__ void gather_cls_k(const __half* __restrict__ ctxh,
                             const float* __restrict__ x,
                             __half* __restrict__ c8h,
                             float* __restrict__ x8)
{
    int b = blockIdx.x, tid = threadIdx.x;
#pragma unroll
    for (int p = 0; p < 2; p++) {
        int d = tid + p * 256;
        c8h[(long)b * D_ + d] = ctxh[((long)b * SEQ_) * D_ + d];
        x8[(long)b * D_ + d]  = x[((long)b * SEQ_) * D_ + d];
    }
}

// ---------------- warp-per-row layernorm --------------------------------------
__global__ void ln_w(const float* __restrict__ in, float* __restrict__ out,
                     __half* __restrict__ outh,
                     const float* __restrict__ g, const float* __restrict__ bb)
{
    const int w = threadIdx.x >> 5, lane = threadIdx.x & 31;
    const long t = (long)blockIdx.x * 8 + w;
    const float* x = in + t * D_;

    float4 v[4];
    float s = 0.f;
#pragma unroll
    for (int i = 0; i < 4; i++) {
        v[i] = *(const float4*)(x + lane * 4 + i * 128);
        s += (v[i].x + v[i].y) + (v[i].z + v[i].w);
    }
#pragma unroll
    for (int o = 16; o > 0; o >>= 1) s += __shfl_xor_sync(0xffffffffu, s, o);
    const float mean = s * (1.f / D_);

    float var = 0.f;
#pragma unroll
    for (int i = 0; i < 4; i++) {
        float dx = v[i].x - mean, dy = v[i].y - mean;
        float dz = v[i].z - mean, dw = v[i].w - mean;
        var += (dx * dx + dy * dy) + (dz * dz + dw * dw);
    }
#pragma unroll
    for (int o = 16; o > 0; o >>= 1) var += __shfl_xor_sync(0xffffffffu, var, o);
    const float rstd = rsqrtf(var * (1.f / D_) + 1e-6f);

    float* o_ = out + t * D_;
    __half* oh = outh + t * D_;
#pragma unroll
    for (int i = 0; i < 4; i++) {
        int d = lane * 4 + i * 128;
        float4 gv = *(const float4*)(g + d);
        float4 bv = *(const float4*)(bb + d);
        float4 r;
        r.x = (v[i].x - mean) * rstd * gv.x + bv.x;
        r.y = (v[i].y - mean) * rstd * gv.y + bv.y;
        r.z = (v[i].z - mean) * rstd * gv.z + bv.z;
        r.w = (v[i].w - mean) * rstd * gv.w + bv.w;
        *(float4*)(o_ + d) = r;
        __half2 h0 = __floats2half2_rn(r.x, r.y);
        __half2 h1 = __floats2half2_rn(r.z, r.w);
        *(uint2*)(oh + d) = make_uint2(*(uint32_t*)&h0, *(uint32_t*)&h1);
    }
}

// ---------------- MLP head on compact cls rows --------------------------------
__global__ void head_k(const float* __restrict__ x8,
                       const float* __restrict__ w1,
                       const float* __restrict__ w2,
                       float* __restrict__ out)
{
    int b = blockIdx.x;
    int tid = threadIdx.x;
    __shared__ float cls[D_];
    __shared__ float red[256];
    for (int i = tid; i < D_; i += 256)
        cls[i] = x8[(long)b * D_ + i];
    __syncthreads();

    float partial = 0.f;
    for (int j = tid; j < DMLP_; j += 256) {
        const float* w = w1 + (long)j * D_;
        float s = 0.f;
#pragma unroll 8
        for (int k = 0; k < D_; k++) s += cls[k] * w[k];
        partial += gelu_exact(s) * w2[j];
    }
    red[tid] = partial; __syncthreads();
    for (int k = 128; k > 0; k >>= 1) {
        if (tid < k) red[tid] += red[tid + k];
        __syncthreads();
    }
    if (tid == 0) out[b] = red[0];
}

// =============================================================================
extern "C" void kernel_launch(void* const* d_in, const int* in_sizes, int n_in,
                              void* d_out, int out_size)
{
    const float* feat_org = (const float*)d_in[0];
    const float* feat_r1  = (const float*)d_in[1];
    const float* feat_r2  = (const float*)d_in[2];
    const float* conv_w   = (const float*)d_in[3];
    const float* conv_b   = (const float*)d_in[4];
    const float* org_emb  = (const float*)d_in[5];
    const float* r1_emb   = (const float*)d_in[6];
    const float* r2_emb   = (const float*)d_in[7];
    const float* pos_emb  = (const float*)d_in[8];
    const float* cls_tok  = (const float*)d_in[9];
    const float* Wq = (const float*)d_in[10];
    const float* bq = (const float*)d_in[11];
    const float* Wk = (const float*)d_in[12];
    const float* bk = (const float*)d_in[13];
    const float* Wv = (const float*)d_in[14];
    const float* bv = (const float*)d_in[15];
    const float* Wo = (const float*)d_in[16];
    const float* bo = (const float*)d_in[17];
    const float* ln1g = (const float*)d_in[18];
    const float* ln1b = (const float*)d_in[19];
    const float* w1 = (const float*)d_in[20];
    const float* b1 = (const float*)d_in[21];
    const float* w2 = (const float*)d_in[22];
    const float* b2 = (const float*)d_in[23];
    const float* ln2g = (const float*)d_in[24];
    const float* ln2b = (const float*)d_in[25];
    const float* pw1 = (const float*)d_in[26];
    const float* pw2 = (const float*)d_in[27];
    const int*   mask = (const int*)d_in[28];
    float* out = (float*)d_out;

    __half *Ah, *xh, *qkvh, *ctxh, *ffh, *wqkv, *woh, *w1h, *w2h, *cwh;
    __half *c8h, *x8h, *f8h;
    float *addv, *x, *tmp, *x8, *t8;
    cudaGetSymbolAddress((void**)&Ah, g_Ah);
    cudaGetSymbolAddress((void**)&addv, g_add);
    cudaGetSymbolAddress((void**)&x, g_x);
    cudaGetSymbolAddress((void**)&xh, g_xh);
    cudaGetSymbolAddress((void**)&tmp, g_tmp);
    cudaGetSymbolAddress((void**)&qkvh, g_qkvh);
    cudaGetSymbolAddress((void**)&ctxh, g_ctxh);
    cudaGetSymbolAddress((void**)&ffh, g_ffh);
    cudaGetSymbolAddress((void**)&wqkv, g_wqkv);
    cudaGetSymbolAddress((void**)&woh, g_woh);
    cudaGetSymbolAddress((void**)&w1h, g_w1h);
    cudaGetSymbolAddress((void**)&w2h, g_w2h);
    cudaGetSymbolAddress((void**)&cwh, g_cwh);
    cudaGetSymbolAddress((void**)&c8h, g_c8h);
    cudaGetSymbolAddress((void**)&x8, g_x8);
    cudaGetSymbolAddress((void**)&t8, g_t8);
    cudaGetSymbolAddress((void**)&x8h, g_x8h);
    cudaGetSymbolAddress((void**)&f8h, g_f8h);

    const int G64 = GSMEM_FOR(64);
    cudaFuncSetAttribute(flashm_k, cudaFuncAttributeMaxDynamicSharedMemorySize, FSMEM);
    cudaFuncSetAttribute(gemm_cp<64, 1>, cudaFuncAttributeMaxDynamicSharedMemorySize, G64);
    cudaFuncSetAttribute(gemm_cp<64, 5>, cudaFuncAttributeMaxDynamicSharedMemorySize, G64);
    cudaFuncSetAttribute(gemm_cp<64, 6>, cudaFuncAttributeMaxDynamicSharedMemorySize, G64);
    cudaFuncSetAttribute(gemm_cp<64, 7>, cudaFuncAttributeMaxDynamicSharedMemorySize, G64);

    // launch order: #4 = embed GEMM so the ncu capture window profiles gemm_cp
    transpose_all_k<<<dim3(30, CIN_ / 32, B_), dim3(32, 8)>>>(feat_org, feat_r1,
                                                              feat_r2, Ah);
    addvec_k<<<NTOK_, D_>>>(conv_b, org_emb, r1_emb, r2_emb, pos_emb, addv);
    stage_k<<<2048, 256>>>(conv_w, Wo, w1, w2, Wq, Wk, Wv,
                           cwh, woh, w1h, w2h, wqkv);
    gemm_cp<64, 7><<<dim3(8, 57), 256, G64>>>(Ah, cwh, x, xh, B_ * NTOK_, D_, CIN_,
                                              nullptr, nullptr, addv);
    cls_k<<<B_, D_>>>(cls_tok, x, xh);

    const float scale = 0.125f;  // 1/sqrt(64)
    for (int i = 0; i < L_ - 1; i++) {
        gemm_cp<64, 1><<<dim3(24, 57), 256, G64>>>(xh, wqkv + (long)i * 3 * D_ * D_,
                                                   nullptr, qkvh, B_ * SEQ_, 3 * D_, D_,
                                                   bq + i * D_, bk + i * D_, bv + i * D_);

        flashm_k<<<dim3(NKV, B_ * H_), 128, FSMEM>>>(
            qkvh, qkvh + QKVOFF, qkvh + 2 * QKVOFF, ctxh, mask, scale);

        gemm_cp<64, 5><<<dim3(8, 57), 256, G64>>>(ctxh, woh + (long)i * D_ * D_,
                                                  tmp, nullptr, B_ * SEQ_, D_, D_,
                                                  bo + i * D_, x, nullptr);
        ln_w<<<B_ * SEQ_ / 8, 256>>>(tmp, x, xh, ln1g + i * D_, ln1b + i * D_);

        gemm_cp<64, 6><<<dim3(32, 57), 256, G64>>>(xh, w1h + (long)i * DFF_ * D_,
                                                   nullptr, ffh, B_ * SEQ_, DFF_, D_,
                                                   b1 + i * DFF_, nullptr, nullptr);
        gemm_cp<64, 5><<<dim3(8, 57), 256, G64>>>(ffh, w2h + (long)i * D_ * DFF_,
                                                  tmp, nullptr, B_ * SEQ_, D_, DFF_,
                                                  b2 + i * D_, x, nullptr);
        ln_w<<<B_ * SEQ_ / 8, 256>>>(tmp, x, xh, ln2g + i * D_, ln2b + i * D_);
    }

    // ---- last layer: only cls tokens matter after attention ----
    {
        const int i = L_ - 1;
        gemm_cp<64, 1><<<dim3(24, 57), 256, G64>>>(xh, wqkv + (long)i * 3 * D_ * D_,
                                                   nullptr, qkvh, B_ * SEQ_, 3 * D_, D_,
                                                   bq + i * D_, bk + i * D_, bv + i * D_);
        flashm_k<<<dim3(1, B_ * H_), 128, FSMEM>>>(
            qkvh, qkvh + QKVOFF, qkvh + 2 * QKVOFF, ctxh, mask, scale);

        gather_cls_k<<<B_, 256>>>(ctxh, x, c8h, x8);

        gemm_cp<64, 5><<<dim3(8, 1), 256, G64>>>(c8h, woh + (long)i * D_ * D_,
                                                 t8, nullptr, B_, D_, D_,
                                                 bo + i * D_, x8, nullptr);
        ln_w<<<1, 256>>>(t8, x8, x8h, ln1g + i * D_, ln1b + i * D_);

        gemm_cp<64, 6><<<dim3(32, 1), 256, G64>>>(x8h, w1h + (long)i * DFF_ * D_,
                                                  nullptr, f8h, B_, DFF_, D_,
                                                  b1 + i * DFF_, nullptr, nullptr);
        gemm_cp<64, 5><<<dim3(8, 1), 256, G64>>>(f8h, w2h + (long)i * D_ * DFF_,
                                                 t8, nullptr, B_, D_, DFF_,
                                                 b2 + i * D_, x8, nullptr);
        ln_w<<<1, 256>>>(t8, x8, x8h, ln2g + i * D_, ln2b + i * D_);
    }

    head_k<<<B_, 256>>>(x8, pw1, pw2, out);
}

// round 15
// speedup vs baseline: 1.1117x; 1.0130x over previous
#include <cuda_runtime.h>
#include <cuda_fp16.h>
#include <math.h>
#include <stdint.h>

#define B_    8
#define D_    512
#define H_    8
#define DH_   64
#define L_    6
#define DFF_  2048
#define CIN_  2048
#define SEQ_  912
#define NTOK_ 911
#define DMLP_ 1024
#define QKVOFF ((long)B_ * SEQ_ * D_)

// ---------------- scratch (static device globals; allocation-free) ----------
__device__ __align__(16) __half g_Ah[(size_t)B_ * NTOK_ * CIN_];
__device__ __align__(16) float  g_add[(size_t)NTOK_ * D_];
__device__ __align__(16) float  g_x[(size_t)B_ * SEQ_ * D_];
__device__ __align__(16) __half g_xh[(size_t)B_ * SEQ_ * D_];
__device__ __align__(16) float  g_tmp[(size_t)B_ * SEQ_ * D_];
__device__ __align__(16) __half g_qkvh[3 * (size_t)B_ * SEQ_ * D_];
__device__ __align__(16) __half g_ctxh[(size_t)B_ * SEQ_ * D_];
__device__ __align__(16) __half g_ffh[(size_t)B_ * SEQ_ * DFF_];
__device__ __align__(16) __half g_wqkv[(size_t)L_ * 3 * D_ * D_];
__device__ __align__(16) __half g_woh[(size_t)L_ * D_ * D_];
__device__ __align__(16) __half g_w1h[(size_t)L_ * DFF_ * D_];
__device__ __align__(16) __half g_w2h[(size_t)L_ * D_ * DFF_];
__device__ __align__(16) __half g_cwh[(size_t)D_ * CIN_];
// last-layer compact cls-path buffers
__device__ __align__(16) __half g_c8h[(size_t)B_ * D_];
__device__ __align__(16) float  g_x8[(size_t)B_ * D_];
__device__ __align__(16) float  g_t8[(size_t)B_ * D_];
__device__ __align__(16) __half g_x8h[(size_t)B_ * D_];
__device__ __align__(16) __half g_f8h[(size_t)B_ * DFF_];

__device__ __forceinline__ float gelu_exact(float x) {
    return 0.5f * x * (1.0f + erff(x * 0.70710678118654752f));
}
__device__ __forceinline__ uint32_t smem_u32(const void* p) {
    uint32_t a;
    asm("{ .reg .u64 t; cvta.to.shared.u64 t, %1; cvt.u32.u64 %0, t; }"
        : "=r"(a) : "l"(p));
    return a;
}
__device__ __forceinline__ uint32_t packh2(float x, float y) {
    __half2 h = __floats2half2_rn(x, y);
    return *(uint32_t*)&h;
}
__device__ __forceinline__ void mma_f16(float c[4], const uint32_t a[4],
                                        uint32_t b0, uint32_t b1) {
    asm volatile(
        "mma.sync.aligned.m16n8k16.row.col.f32.f16.f16.f32 "
        "{%0,%1,%2,%3}, {%4,%5,%6,%7}, {%8,%9}, {%0,%1,%2,%3};"
        : "+f"(c[0]), "+f"(c[1]), "+f"(c[2]), "+f"(c[3])
        : "r"(a[0]), "r"(a[1]), "r"(a[2]), "r"(a[3]), "r"(b0), "r"(b1));
}
#define LDSM_X4(r, addr) \
    asm volatile("ldmatrix.sync.aligned.m8n8.x4.shared.b16 {%0,%1,%2,%3}, [%4];" \
        : "=r"((r)[0]), "=r"((r)[1]), "=r"((r)[2]), "=r"((r)[3]) : "r"(addr))
#define LDSM_X4_T(r, addr) \
    asm volatile("ldmatrix.sync.aligned.m8n8.x4.trans.shared.b16 {%0,%1,%2,%3}, [%4];" \
        : "=r"((r)[0]), "=r"((r)[1]), "=r"((r)[2]), "=r"((r)[3]) : "r"(addr))
#define CP_ASYNC(dst, src, sz) \
    asm volatile("cp.async.cg.shared.global [%0], [%1], 16, %2;" \
                 :: "r"(dst), "l"(src), "r"(sz) : "memory")
#define CP_COMMIT() asm volatile("cp.async.commit_group;" ::: "memory")
#define CP_WAIT2()  asm volatile("cp.async.wait_group 2;" ::: "memory")
#define CP_WAIT1()  asm volatile("cp.async.wait_group 1;" ::: "memory")
#define CP_WAIT0()  asm volatile("cp.async.wait_group 0;" ::: "memory")

// ---------------- single staging kernel: all weights -> half -----------------
__global__ void stage_k(const float* __restrict__ conv_w,
                        const float* __restrict__ Wo,
                        const float* __restrict__ w1,
                        const float* __restrict__ w2,
                        const float* __restrict__ Wq,
                        const float* __restrict__ Wk,
                        const float* __restrict__ Wv,
                        __half* __restrict__ cwh, __half* __restrict__ woh,
                        __half* __restrict__ w1h, __half* __restrict__ w2h,
                        __half* __restrict__ wqkv)
{
    const long n0 = (long)D_ * CIN_ / 4;
    const long n1 = (long)L_ * D_ * D_ / 4;
    const long n2 = (long)L_ * DFF_ * D_ / 4;
    const long n3 = (long)L_ * D_ * DFF_ / 4;
    const long n4 = (long)L_ * 3 * D_ * D_ / 4;
    const long total = n0 + n1 + n2 + n3 + n4;
    const long per = (long)D_ * D_ / 4;

    for (long i = (long)blockIdx.x * blockDim.x + threadIdx.x; i < total;
         i += (long)gridDim.x * blockDim.x) {
        const float* src;
        __half* dst;
        long so, dd;
        if (i < n0)                { src = conv_w; dst = cwh; so = i; dd = i; }
        else if (i < n0 + n1)      { src = Wo; dst = woh; so = i - n0; dd = so; }
        else if (i < n0 + n1 + n2) { src = w1; dst = w1h; so = i - n0 - n1; dd = so; }
        else if (i < n0 + n1 + n2 + n3) {
            src = w2; dst = w2h; so = i - n0 - n1 - n2; dd = so;
        } else {
            long r = i - n0 - n1 - n2 - n3;
            long l = r / (3 * per);
            long q = (r / per) % 3;
            long o = r % per;
            src = (q == 0 ? Wq : (q == 1 ? Wk : Wv));
            so = l * per + o;
            dst = wqkv; dd = r;
        }
        float4 v = *((const float4*)src + so);
        __half2* d = (__half2*)(dst + dd * 4);
        d[0] = __floats2half2_rn(v.x, v.y);
        d[1] = __floats2half2_rn(v.z, v.w);
    }
}

// ---------------- cp.async + ldmatrix FP16 GEMM: C = A(MxK)*B(NxK)^T ---------
// BM=128, BN=64; 8 warps as 4(row)x2(col): warp tile 32x32.
// Per warp-step: 2 A-LDSM + 2 B-LDSM feed 8 MMAs (was 5:8) -> ~20% less L1.
#define STAGES 3
#define TILEA  16384
#define GSMEM_FOR(BN) (STAGES * (TILEA + (BN) * 128))

template <int BN, int MODE>
__global__ __launch_bounds__(256, 3) void gemm_cp(
    const __half* __restrict__ A, const __half* __restrict__ Bm,
    float* __restrict__ C, __half* __restrict__ Ch, int M, int N, int K,
    const float* __restrict__ bias,
    const float* __restrict__ res,
    const float* __restrict__ rowadd)
{
    constexpr int WN    = BN / 2;           // warp col span (32)
    constexpr int NB16  = WN / 16;          // 16-col b-tiles per warp (2)
    constexpr int NT    = 2 * NB16;         // 8-col n-tiles per warp (4)
    constexpr int MT    = 2;                // 16-row a-tiles per warp
    constexpr int TILEBB = BN * 128;
    constexpr int STAGEB = TILEA + TILEBB;
    constexpr int BPASS  = BN / 32;

    extern __shared__ char smraw[];
    const uint32_t sb = smem_u32(smraw);
    const int tid  = threadIdx.x;
    const int lane = tid & 31;
    const int wid  = tid >> 5;
    const int wm   = wid & 3;              // 0..3: 32-row group
    const int wn   = wid >> 2;             // 0..1: 32-col group
    const int row0 = blockIdx.y * 128;
    const int col0 = blockIdx.x * BN;

    const int ldr = tid >> 3;
    const int ldc = tid & 7;

    float acc[MT][NT][4];
#pragma unroll
    for (int i = 0; i < MT; i++)
#pragma unroll
        for (int j = 0; j < NT; j++)
#pragma unroll
            for (int e = 0; e < 4; e++) acc[i][j][e] = 0.f;

    const int kIters = K / 64;

    auto issue = [&](int it) {
        const uint32_t soff = (uint32_t)(it % STAGES) * STAGEB;
        const long kh = (long)it * 64 + ldc * 8;
#pragma unroll
        for (int pass = 0; pass < 4; pass++) {
            int row = ldr + pass * 32;
            uint32_t pc = (uint32_t)((ldc ^ (row & 7)) * 16);
            uint32_t sa = sb + soff + row * 128 + pc;
            const __half* ga = A + (long)(row0 + row) * K + kh;
            int sza = (row0 + row < M) ? 16 : 0;
            CP_ASYNC(sa, ga, sza);
        }
#pragma unroll
        for (int pass = 0; pass < BPASS; pass++) {
            int row = ldr + pass * 32;
            uint32_t pc = (uint32_t)((ldc ^ (row & 7)) * 16);
            uint32_t sbb = sb + soff + TILEA + row * 128 + pc;
            const __half* gb = Bm + (long)(col0 + row) * K + kh;
            int szb = (col0 + row < N) ? 16 : 0;
            CP_ASYNC(sbb, gb, szb);
        }
        CP_COMMIT();
    };

    issue(0);
    issue(1);

    const int arow = ((lane >> 3) & 1) * 8 + (lane & 7);
    const int chi  = lane >> 4;

    for (int it = 0; it < kIters; ++it) {
        CP_WAIT1();
        __syncthreads();
        if (it + 2 < kIters) issue(it + 2);
        else CP_COMMIT();

        const uint32_t base = sb + (uint32_t)(it % STAGES) * STAGEB;

#pragma unroll
        for (int s = 0; s < 4; s++) {
            const int ch = 2 * s + chi;
            uint32_t afr[MT][4], bfr[NB16][4];
#pragma unroll
            for (int im = 0; im < MT; im++) {
                int row = wm * 32 + im * 16 + arow;
                uint32_t addr = base + row * 128 + ((ch ^ (row & 7)) * 16);
                LDSM_X4(afr[im], addr);
            }
#pragma unroll
            for (int jb = 0; jb < NB16; jb++) {
                int rowb = wn * WN + jb * 16 + arow;
                uint32_t addr = base + TILEA + rowb * 128 + ((ch ^ (rowb & 7)) * 16);
                LDSM_X4(bfr[jb], addr);
            }
#pragma unroll
            for (int im = 0; im < MT; im++) {
#pragma unroll
                for (int jb = 0; jb < NB16; jb++) {
                    mma_f16(acc[im][2 * jb],     afr[im], bfr[jb][0], bfr[jb][2]);
                    mma_f16(acc[im][2 * jb + 1], afr[im], bfr[jb][1], bfr[jb][3]);
                }
            }
        }
    }
    CP_WAIT0();

    // ---------------- vectorized epilogue (pairs n, n+1) ----------------
    const int rq = lane >> 2;
    const int c  = lane & 3;
#pragma unroll
    for (int im = 0; im < MT; im++) {
        const int m0 = row0 + wm * 32 + im * 16 + rq;
#pragma unroll
        for (int jn = 0; jn < NT; jn++) {
            const int n0 = col0 + wn * WN + jn * 8 + c * 2;
            if (n0 >= N) continue;
#pragma unroll
            for (int hh = 0; hh < 2; hh++) {
                const int m = m0 + hh * 8;
                if (m >= M) continue;
                const float v0 = acc[im][jn][hh * 2];
                const float v1 = acc[im][jn][hh * 2 + 1];
                if constexpr (MODE == 1) {
                    int which = n0 >> 9;
                    int nn = n0 & 511;
                    const float* bp =
                        (which == 0) ? bias : ((which == 1) ? res : rowadd);
                    float2 bv = *(const float2*)(bp + nn);
                    int b = m / SEQ_, s = m - b * SEQ_;
                    int h = nn >> 6, dh = nn & 63;
                    *(__half2*)(Ch + (long)which * QKVOFF +
                                (((long)b * H_ + h) * SEQ_ + s) * DH_ + dh) =
                        __floats2half2_rn(v0 + bv.x, v1 + bv.y);
                } else if constexpr (MODE == 5) {
                    long idx = (long)m * N + n0;
                    float2 bv = *(const float2*)(bias + n0);
                    float2 rv = *(const float2*)(res + idx);
                    *(float2*)(C + idx) =
                        make_float2(v0 + bv.x + rv.x, v1 + bv.y + rv.y);
                } else if constexpr (MODE == 6) {
                    float2 bv = *(const float2*)(bias + n0);
                    *(__half2*)(Ch + (long)m * N + n0) = __floats2half2_rn(
                        gelu_exact(v0 + bv.x), gelu_exact(v1 + bv.y));
                } else if constexpr (MODE == 7) {
                    int b = m / NTOK_, p = m - b * NTOK_;
                    float2 rv = *(const float2*)(rowadd + (long)p * D_ + n0);
                    float f0 = v0 + rv.x, f1 = v1 + rv.y;
                    long idx = ((long)(b * SEQ_ + 1 + p)) * D_ + n0;
                    *(float2*)(C + idx) = make_float2(f0, f1);
                    *(__half2*)(Ch + idx) = __floats2half2_rn(f0, f1);
                }
            }
        }
    }
}

// ---------------- tensor-core flash attention (fp16 mma, fp32 softmax) -------
// 64 q-rows, 128 threads, 4 warps; K/V/mask cp.async 3-slot ring.
#define FQ_OFF 0
#define FK_OFF 8192
#define FV_OFF 32768
#define FM_OFF 57344
#define FSMEM  58112
#define NKV 15

__global__ __launch_bounds__(128, 3) void flashm_k(
    const __half* __restrict__ qg, const __half* __restrict__ kg,
    const __half* __restrict__ vg, __half* __restrict__ ctx,
    const int* __restrict__ mask, float scale)
{
    extern __shared__ char smraw[];
    const uint32_t sb = smem_u32(smraw);
    const int tid = threadIdx.x;
    const int lane = tid & 31;
    const int w = tid >> 5;
    const int z = blockIdx.y;
    const int b = z >> 3;
    const int h = z & 7;
    const int q0 = blockIdx.x * 64;
    const long base = (long)z * SEQ_ * DH_;
    const int mbase = b * SEQ_;

    const int arow = ((lane >> 3) & 1) * 8 + (lane & 7);
    const int chi  = lane >> 4;
    const int rq = lane >> 2;
    const int c  = lane & 3;

#pragma unroll
    for (int p = 0; p < 4; p++) {
        int idx = tid + p * 128;
        int row = idx >> 3, cc = idx & 7;
        uint32_t dst = sb + FQ_OFF + row * 128 + ((cc ^ (row & 7)) * 16);
        const __half* src = qg + base + (long)(q0 + row) * DH_ + cc * 8;
        CP_ASYNC(dst, src, (q0 + row < SEQ_) ? 16 : 0);
    }
    CP_COMMIT();

    auto issue_kv = [&](int t) {
        const int slot = t % 3;
        const uint32_t ko = sb + FK_OFF + slot * 8192;
        const uint32_t vo = sb + FV_OFF + slot * 8192;
#pragma unroll
        for (int p = 0; p < 4; p++) {
            int idx = tid + p * 128;
            int row = idx >> 3, cc = idx & 7;
            uint32_t pc = (uint32_t)((cc ^ (row & 7)) * 16);
            int s = t * 64 + row;
            int sz = (s < SEQ_) ? 16 : 0;
            CP_ASYNC(ko + row * 128 + pc, kg + base + (long)s * DH_ + cc * 8, sz);
            CP_ASYNC(vo + row * 128 + pc, vg + base + (long)s * DH_ + cc * 8, sz);
        }
        if (tid < 16) {
            int rem = SEQ_ - (t * 64 + tid * 4);
            int sz = rem >= 4 ? 16 : (rem > 0 ? rem * 4 : 0);
            CP_ASYNC(sb + FM_OFF + slot * 256 + tid * 16,
                     mask + mbase + t * 64 + tid * 4, sz);
        }
        CP_COMMIT();
    };
    issue_kv(0);
    issue_kv(1);

    CP_WAIT2();
    __syncthreads();
    uint32_t aq[4][4];
#pragma unroll
    for (int s = 0; s < 4; s++) {
        int row = w * 16 + arow;
        int ch = 2 * s + chi;
        LDSM_X4(aq[s], sb + FQ_OFF + row * 128 + ((ch ^ (row & 7)) * 16));
    }

    float m_lo = -1e30f, m_hi = -1e30f, l_lo = 0.f, l_hi = 0.f;
    float o[8][4];
#pragma unroll
    for (int nt = 0; nt < 8; nt++)
#pragma unroll
        for (int e = 0; e < 4; e++) o[nt][e] = 0.f;

    for (int t = 0; t < NKV; t++) {
        CP_WAIT1();
        __syncthreads();
        if (t + 2 < NKV) issue_kv(t + 2);
        else CP_COMMIT();

        const int slot = t % 3;
        const uint32_t kb = sb + FK_OFF + slot * 8192;
        const uint32_t vb = sb + FV_OFF + slot * 8192;
        const int* msk = (const int*)(smraw + FM_OFF + slot * 256);

        float sc[8][4];
#pragma unroll
        for (int j = 0; j < 8; j++)
#pragma unroll
            for (int e = 0; e < 4; e++) sc[j][e] = 0.f;
#pragma unroll
        for (int s = 0; s < 4; s++) {
            const int ch = 2 * s + chi;
#pragma unroll
            for (int jb = 0; jb < 4; jb++) {
                int rowb = jb * 16 + arow;
                uint32_t bk[4];
                LDSM_X4(bk, kb + rowb * 128 + ((ch ^ (rowb & 7)) * 16));
                mma_f16(sc[2 * jb],     aq[s], bk[0], bk[2]);
                mma_f16(sc[2 * jb + 1], aq[s], bk[1], bk[3]);
            }
        }

#pragma unroll
        for (int j = 0; j < 8; j++) {
            int col0 = j * 8 + 2 * c;
            bool ok0 = msk[col0] != 0;
            bool ok1 = msk[col0 + 1] != 0;
            sc[j][0] = ok0 ? sc[j][0] * scale : -1e9f;
            sc[j][1] = ok1 ? sc[j][1] * scale : -1e9f;
            sc[j][2] = ok0 ? sc[j][2] * scale : -1e9f;
            sc[j][3] = ok1 ? sc[j][3] * scale : -1e9f;
        }

        float rm_lo = -1e30f, rm_hi = -1e30f;
#pragma unroll
        for (int j = 0; j < 8; j++) {
            rm_lo = fmaxf(rm_lo, fmaxf(sc[j][0], sc[j][1]));
            rm_hi = fmaxf(rm_hi, fmaxf(sc[j][2], sc[j][3]));
        }
        rm_lo = fmaxf(rm_lo, __shfl_xor_sync(0xffffffffu, rm_lo, 1));
        rm_lo = fmaxf(rm_lo, __shfl_xor_sync(0xffffffffu, rm_lo, 2));
        rm_hi = fmaxf(rm_hi, __shfl_xor_sync(0xffffffffu, rm_hi, 1));
        rm_hi = fmaxf(rm_hi, __shfl_xor_sync(0xffffffffu, rm_hi, 2));

        float mn_lo = fmaxf(m_lo, rm_lo), mn_hi = fmaxf(m_hi, rm_hi);
        float corr_lo = expf(m_lo - mn_lo), corr_hi = expf(m_hi - mn_hi);
        m_lo = mn_lo; m_hi = mn_hi;

        uint32_t ap[4][4];
        float sum_lo = 0.f, sum_hi = 0.f;
#pragma unroll
        for (int j = 0; j < 8; j++) {
            float p0 = expf(sc[j][0] - m_lo);
            float p1 = expf(sc[j][1] - m_lo);
            float p2 = expf(sc[j][2] - m_hi);
            float p3 = expf(sc[j][3] - m_hi);
            sum_lo += p0 + p1;
            sum_hi += p2 + p3;
            int s = j >> 1;
            if ((j & 1) == 0) {
                ap[s][0] = packh2(p0, p1);
                ap[s][1] = packh2(p2, p3);
            } else {
                ap[s][2] = packh2(p0, p1);
                ap[s][3] = packh2(p2, p3);
            }
        }
        sum_lo += __shfl_xor_sync(0xffffffffu, sum_lo, 1);
        sum_lo += __shfl_xor_sync(0xffffffffu, sum_lo, 2);
        sum_hi += __shfl_xor_sync(0xffffffffu, sum_hi, 1);
        sum_hi += __shfl_xor_sync(0xffffffffu, sum_hi, 2);
        l_lo = l_lo * corr_lo + sum_lo;
        l_hi = l_hi * corr_hi + sum_hi;
#pragma unroll
        for (int nt = 0; nt < 8; nt++) {
            o[nt][0] *= corr_lo; o[nt][1] *= corr_lo;
            o[nt][2] *= corr_hi; o[nt][3] *= corr_hi;
        }

#pragma unroll
        for (int s = 0; s < 4; s++) {
#pragma unroll
            for (int g = 0; g < 4; g++) {
                int rowv = s * 16 + arow;
                int ch = 2 * g + chi;
                uint32_t bv[4];
                LDSM_X4_T(bv, vb + rowv * 128 + ((ch ^ (rowv & 7)) * 16));
                mma_f16(o[2 * g],     ap[s], bv[0], bv[1]);
                mma_f16(o[2 * g + 1], ap[s], bv[2], bv[3]);
            }
        }
    }
    CP_WAIT0();

    const float inv_lo = 1.f / l_lo;
    const float inv_hi = 1.f / l_hi;
    const int r_lo = q0 + w * 16 + rq;
    const int r_hi = r_lo + 8;
#pragma unroll
    for (int nt = 0; nt < 8; nt++) {
        int col = h * DH_ + nt * 8 + 2 * c;
        if (r_lo < SEQ_) {
            __half2 hv = __floats2half2_rn(o[nt][0] * inv_lo, o[nt][1] * inv_lo);
            *(__half2*)(ctx + ((long)(b * SEQ_ + r_lo)) * D_ + col) = hv;
        }
        if (r_hi < SEQ_) {
            __half2 hv = __floats2half2_rn(o[nt][2] * inv_hi, o[nt][3] * inv_hi);
            *(__half2*)(ctx + ((long)(b * SEQ_ + r_hi)) * D_ + col) = hv;
        }
    }
}

// ---------------- fused feature transpose -> half ----------------------------
__global__ void transpose_all_k(const float* __restrict__ f0,
                                const float* __restrict__ f1,
                                const float* __restrict__ f2,
                                __half* __restrict__ Aout)
{
    __shared__ float tile[32][33];
    const int bx = blockIdx.x;
    const float* feat;
    int HW, tokoff, hw0;
    if (bx < 24)      { feat = f0; HW = 768; tokoff = 0;   hw0 = bx * 32; }
    else if (bx < 28) { feat = f1; HW = 108; tokoff = 768; hw0 = (bx - 24) * 32; }
    else              { feat = f2; HW = 35;  tokoff = 876; hw0 = (bx - 28) * 32; }

    const int b = blockIdx.z;
    const int c0 = blockIdx.y * 32;
    const int tx = threadIdx.x, ty = threadIdx.y;

    const float* fb = feat + ((long)b * CIN_ + c0) * HW;
#pragma unroll
    for (int i = ty; i < 32; i += 8) {
        int hw = hw0 + tx;
        tile[i][tx] = (hw < HW) ? fb[(long)i * HW + hw] : 0.f;
    }
    __syncthreads();
#pragma unroll
    for (int i = ty; i < 32; i += 8) {
        int hw = hw0 + i;
        if (hw < HW)
            Aout[((long)(b * NTOK_ + tokoff + hw)) * CIN_ + c0 + tx] =
                __float2half(tile[tx][i]);
    }
}

__global__ void addvec_k(const float* __restrict__ conv_b,
                         const float* __restrict__ org_emb,
                         const float* __restrict__ r1_emb,
                         const float* __restrict__ r2_emb,
                         const float* __restrict__ pos_emb,
                         float* __restrict__ addv)
{
    int p = blockIdx.x;
    int d = threadIdx.x;
    int ti, tj;
    const float* emb;
    if (p < 768) {
        int h = p / 32, w = p - h * 32;
        ti = h * 10 / 24; tj = w * 10 / 32; emb = org_emb;
    } else if (p < 876) {
        int pp = p - 768;
        int h = pp / 12, w = pp - h * 12;
        ti = h * 10 / 9; tj = w * 10 / 12; emb = r1_emb;
    } else {
        int pp = p - 876;
        int h = pp / 7, w = pp - h * 7;
        ti = h * 10 / 5; tj = w * 10 / 7; emb = r2_emb;
    }
    addv[(long)p * D_ + d] = conv_b[d] + emb[d] + pos_emb[((long)ti * 10 + tj) * D_ + d];
}

__global__ void cls_k(const float* __restrict__ cls_token,
                      float* __restrict__ x, __half* __restrict__ xh)
{
    int b = blockIdx.x, d = threadIdx.x;
    float v = cls_token[d];
    x[((long)b * SEQ_) * D_ + d] = v;
    xh[((long)b * SEQ_) * D_ + d] = __float2half(v);
}

// ---------------- gather cls rows into compact [B, D] buffers ---------------
__global__ void gather_cls_k(const __half* __restrict__ ctxh,
                             const float* __restrict__ x,
                             __half* __restrict__ c8h,
                             float* __restrict__ x8)
{
    int b = blockIdx.x, tid = threadIdx.x;
#pragma unroll
    for (int p = 0; p < 2; p++) {
        int d = tid + p * 256;
        c8h[(long)b * D_ + d] = ctxh[((long)b * SEQ_) * D_ + d];
        x8[(long)b * D_ + d]  = x[((long)b * SEQ_) * D_ + d];
    }
}

// ---------------- warp-per-row layernorm --------------------------------------
__global__ void ln_w(const float* __restrict__ in, float* __restrict__ out,
                     __half* __restrict__ outh,
                     const float* __restrict__ g, const float* __restrict__ bb)
{
    const int w = threadIdx.x >> 5, lane = threadIdx.x & 31;
    const long t = (long)blockIdx.x * 8 + w;
    const float* x = in + t * D_;

    float4 v[4];
    float s = 0.f;
#pragma unroll
    for (int i = 0; i < 4; i++) {
        v[i] = *(const float4*)(x + lane * 4 + i * 128);
        s += (v[i].x + v[i].y) + (v[i].z + v[i].w);
    }
#pragma unroll
    for (int o = 16; o > 0; o >>= 1) s += __shfl_xor_sync(0xffffffffu, s, o);
    const float mean = s * (1.f / D_);

    float var = 0.f;
#pragma unroll
    for (int i = 0; i < 4; i++) {
        float dx = v[i].x - mean, dy = v[i].y - mean;
        float dz = v[i].z - mean, dw = v[i].w - mean;
        var += (dx * dx + dy * dy) + (dz * dz + dw * dw);
    }
#pragma unroll
    for (int o = 16; o > 0; o >>= 1) var += __shfl_xor_sync(0xffffffffu, var, o);
    const float rstd = rsqrtf(var * (1.f / D_) + 1e-6f);

    float* o_ = out + t * D_;
    __half* oh = outh + t * D_;
#pragma unroll
    for (int i = 0; i < 4; i++) {
        int d = lane * 4 + i * 128;
        float4 gv = *(const float4*)(g + d);
        float4 bv = *(const float4*)(bb + d);
        float4 r;
        r.x = (v[i].x - mean) * rstd * gv.x + bv.x;
        r.y = (v[i].y - mean) * rstd * gv.y + bv.y;
        r.z = (v[i].z - mean) * rstd * gv.z + bv.z;
        r.w = (v[i].w - mean) * rstd * gv.w + bv.w;
        *(float4*)(o_ + d) = r;
        __half2 h0 = __floats2half2_rn(r.x, r.y);
        __half2 h1 = __floats2half2_rn(r.z, r.w);
        *(uint2*)(oh + d) = make_uint2(*(uint32_t*)&h0, *(uint32_t*)&h1);
    }
}

// ---------------- MLP head on compact cls rows --------------------------------
__global__ void head_k(const float* __restrict__ x8,
                       const float* __restrict__ w1,
                       const float* __restrict__ w2,
                       float* __restrict__ out)
{
    int b = blockIdx.x;
    int tid = threadIdx.x;
    __shared__ float cls[D_];
    __shared__ float red[256];
    for (int i = tid; i < D_; i += 256)
        cls[i] = x8[(long)b * D_ + i];
    __syncthreads();

    float partial = 0.f;
    for (int j = tid; j < DMLP_; j += 256) {
        const float* w = w1 + (long)j * D_;
        float s = 0.f;
#pragma unroll 8
        for (int k = 0; k < D_; k++) s += cls[k] * w[k];
        partial += gelu_exact(s) * w2[j];
    }
    red[tid] = partial; __syncthreads();
    for (int k = 128; k > 0; k >>= 1) {
        if (tid < k) red[tid] += red[tid + k];
        __syncthreads();
    }
    if (tid == 0) out[b] = red[0];
}

// =============================================================================
extern "C" void kernel_launch(void* const* d_in, const int* in_sizes, int n_in,
                              void* d_out, int out_size)
{
    const float* feat_org = (const float*)d_in[0];
    const float* feat_r1  = (const float*)d_in[1];
    const float* feat_r2  = (const float*)d_in[2];
    const float* conv_w   = (const float*)d_in[3];
    const float* conv_b   = (const float*)d_in[4];
    const float* org_emb  = (const float*)d_in[5];
    const float* r1_emb   = (const float*)d_in[6];
    const float* r2_emb   = (const float*)d_in[7];
    const float* pos_emb  = (const float*)d_in[8];
    const float* cls_tok  = (const float*)d_in[9];
    const float* Wq = (const float*)d_in[10];
    const float* bq = (const float*)d_in[11];
    const float* Wk = (const float*)d_in[12];
    const float* bk = (const float*)d_in[13];
    const float* Wv = (const float*)d_in[14];
    const float* bv = (const float*)d_in[15];
    const float* Wo = (const float*)d_in[16];
    const float* bo = (const float*)d_in[17];
    const float* ln1g = (const float*)d_in[18];
    const float* ln1b = (const float*)d_in[19];
    const float* w1 = (const float*)d_in[20];
    const float* b1 = (const float*)d_in[21];
    const float* w2 = (const float*)d_in[22];
    const float* b2 = (const float*)d_in[23];
    const float* ln2g = (const float*)d_in[24];
    const float* ln2b = (const float*)d_in[25];
    const float* pw1 = (const float*)d_in[26];
    const float* pw2 = (const float*)d_in[27];
    const int*   mask = (const int*)d_in[28];
    float* out = (float*)d_out;

    __half *Ah, *xh, *qkvh, *ctxh, *ffh, *wqkv, *woh, *w1h, *w2h, *cwh;
    __half *c8h, *x8h, *f8h;
    float *addv, *x, *tmp, *x8, *t8;
    cudaGetSymbolAddress((void**)&Ah, g_Ah);
    cudaGetSymbolAddress((void**)&addv, g_add);
    cudaGetSymbolAddress((void**)&x, g_x);
    cudaGetSymbolAddress((void**)&xh, g_xh);
    cudaGetSymbolAddress((void**)&tmp, g_tmp);
    cudaGetSymbolAddress((void**)&qkvh, g_qkvh);
    cudaGetSymbolAddress((void**)&ctxh, g_ctxh);
    cudaGetSymbolAddress((void**)&ffh, g_ffh);
    cudaGetSymbolAddress((void**)&wqkv, g_wqkv);
    cudaGetSymbolAddress((void**)&woh, g_woh);
    cudaGetSymbolAddress((void**)&w1h, g_w1h);
    cudaGetSymbolAddress((void**)&w2h, g_w2h);
    cudaGetSymbolAddress((void**)&cwh, g_cwh);
    cudaGetSymbolAddress((void**)&c8h, g_c8h);
    cudaGetSymbolAddress((void**)&x8, g_x8);
    cudaGetSymbolAddress((void**)&t8, g_t8);
    cudaGetSymbolAddress((void**)&x8h, g_x8h);
    cudaGetSymbolAddress((void**)&f8h, g_f8h);

    const int G64 = GSMEM_FOR(64);
    cudaFuncSetAttribute(flashm_k, cudaFuncAttributeMaxDynamicSharedMemorySize, FSMEM);
    cudaFuncSetAttribute(gemm_cp<64, 1>, cudaFuncAttributeMaxDynamicSharedMemorySize, G64);
    cudaFuncSetAttribute(gemm_cp<64, 5>, cudaFuncAttributeMaxDynamicSharedMemorySize, G64);
    cudaFuncSetAttribute(gemm_cp<64, 6>, cudaFuncAttributeMaxDynamicSharedMemorySize, G64);
    cudaFuncSetAttribute(gemm_cp<64, 7>, cudaFuncAttributeMaxDynamicSharedMemorySize, G64);

    // launch order: #4 = embed GEMM so the ncu capture window profiles gemm_cp
    transpose_all_k<<<dim3(30, CIN_ / 32, B_), dim3(32, 8)>>>(feat_org, feat_r1,
                                                              feat_r2, Ah);
    addvec_k<<<NTOK_, D_>>>(conv_b, org_emb, r1_emb, r2_emb, pos_emb, addv);
    stage_k<<<2048, 256>>>(conv_w, Wo, w1, w2, Wq, Wk, Wv,
                           cwh, woh, w1h, w2h, wqkv);
    gemm_cp<64, 7><<<dim3(8, 57), 256, G64>>>(Ah, cwh, x, xh, B_ * NTOK_, D_, CIN_,
                                              nullptr, nullptr, addv);
    cls_k<<<B_, D_>>>(cls_tok, x, xh);

    const float scale = 0.125f;  // 1/sqrt(64)
    for (int i = 0; i < L_ - 1; i++) {
        gemm_cp<64, 1><<<dim3(24, 57), 256, G64>>>(xh, wqkv + (long)i * 3 * D_ * D_,
                                                   nullptr, qkvh, B_ * SEQ_, 3 * D_, D_,
                                                   bq + i * D_, bk + i * D_, bv + i * D_);

        flashm_k<<<dim3(NKV, B_ * H_), 128, FSMEM>>>(
            qkvh, qkvh + QKVOFF, qkvh + 2 * QKVOFF, ctxh, mask, scale);

        gemm_cp<64, 5><<<dim3(8, 57), 256, G64>>>(ctxh, woh + (long)i * D_ * D_,
                                                  tmp, nullptr, B_ * SEQ_, D_, D_,
                                                  bo + i * D_, x, nullptr);
        ln_w<<<B_ * SEQ_ / 8, 256>>>(tmp, x, xh, ln1g + i * D_, ln1b + i * D_);

        gemm_cp<64, 6><<<dim3(32, 57), 256, G64>>>(xh, w1h + (long)i * DFF_ * D_,
                                                   nullptr, ffh, B_ * SEQ_, DFF_, D_,
                                                   b1 + i * DFF_, nullptr, nullptr);
        gemm_cp<64, 5><<<dim3(8, 57), 256, G64>>>(ffh, w2h + (long)i * D_ * DFF_,
                                                  tmp, nullptr, B_ * SEQ_, D_, DFF_,
                                                  b2 + i * D_, x, nullptr);
        ln_w<<<B_ * SEQ_ / 8, 256>>>(tmp, x, xh, ln2g + i * D_, ln2b + i * D_);
    }

    // ---- last layer: only cls tokens matter after attention ----
    {
        const int i = L_ - 1;
        gemm_cp<64, 1><<<dim3(24, 57), 256, G64>>>(xh, wqkv + (long)i * 3 * D_ * D_,
                                                   nullptr, qkvh, B_ * SEQ_, 3 * D_, D_,
                                                   bq + i * D_, bk + i * D_, bv + i * D_);
        flashm_k<<<dim3(1, B_ * H_), 128, FSMEM>>>(
            qkvh, qkvh + QKVOFF, qkvh + 2 * QKVOFF, ctxh, mask, scale);

        gather_cls_k<<<B_, 256>>>(ctxh, x, c8h, x8);

        gemm_cp<64, 5><<<dim3(8, 1), 256, G64>>>(c8h, woh + (long)i * D_ * D_,
                                                 t8, nullptr, B_, D_, D_,
                                                 bo + i * D_, x8, nullptr);
        ln_w<<<1, 256>>>(t8, x8, x8h, ln1g + i * D_, ln1b + i * D_);

        gemm_cp<64, 6><<<dim3(32, 1), 256, G64>>>(x8h, w1h + (long)i * DFF_ * D_,
                                                  nullptr, f8h, B_, DFF_, D_,
                                                  b1 + i * DFF_, nullptr, nullptr);
        gemm_cp<64, 5><<<dim3(8, 1), 256, G64>>>(f8h, w2h + (long)i * D_ * DFF_,
                                                 t8, nullptr, B_, D_, DFF_,
                                                 b2 + i * D_, x8, nullptr);
        ln_w<<<1, 256>>>(t8, x8, x8h, ln2g + i * D_, ln2b + i * D_);
    }

    head_k<<<B_, 256>>>(x8, pw1, pw2, out);
}